// round 5
// baseline (speedup 1.0000x reference)
#include <cuda_runtime.h>
#include <cuda_bf16.h>
#include <cstdint>

#define B_SZ     4
#define S_LEN    2048
#define D_MODEL  1024
#define NH       16
#define HD       64
#define M_ROWS   (B_SZ * S_LEN)          // 8192

// Scratch (static device globals — no cudaMalloc allowed)
__device__ float g_q[(size_t)M_ROWS * D_MODEL];
__device__ float g_k[(size_t)M_ROWS * D_MODEL];
__device__ float g_v[(size_t)M_ROWS * D_MODEL];
__device__ float g_ctx[(size_t)M_ROWS * D_MODEL];
__device__ float g_l[(size_t)B_SZ * NH * S_LEN];

// ---------------------------------------------------------------------------
// FFMA-only exp(x*0.125)
// ---------------------------------------------------------------------------
__device__ __forceinline__ float fast_exp8(float x)
{
    float t = x * 0.18033688011112042f;            // log2(e)/8
    t = fminf(fmaxf(t, -60.f), 60.f);
    float fi = rintf(t);
    float f  = t - fi;
    float p  = 0.00015403530f;
    p = fmaf(p, f, 0.00133335581f);
    p = fmaf(p, f, 0.00961812911f);
    p = fmaf(p, f, 0.05550410866f);
    p = fmaf(p, f, 0.24022650696f);
    p = fmaf(p, f, 0.69314718056f);
    p = fmaf(p, f, 1.0f);
    int i = (int)fi;
    return p * __int_as_float((i + 127) << 23);
}

// ---------------------------------------------------------------------------
// bf16 helpers
// ---------------------------------------------------------------------------
__device__ __forceinline__ uint32_t pack_bf2(float a, float b)
{
    __nv_bfloat162 h = __floats2bfloat162_rn(a, b);   // a -> low half
    return *reinterpret_cast<uint32_t*>(&h);
}

__device__ __forceinline__ void split_hi_lo(float x, float& hi, float& lo)
{
    __nv_bfloat16 h = __float2bfloat16(x);
    hi = __bfloat162float(h);
    lo = x - hi;
}

__device__ __forceinline__ void mma_bf16(
    float& c0, float& c1, float& c2, float& c3,
    uint32_t a0, uint32_t a1, uint32_t a2, uint32_t a3,
    uint32_t b0, uint32_t b1)
{
    asm volatile(
        "mma.sync.aligned.m16n8k16.row.col.f32.bf16.bf16.f32 "
        "{%0,%1,%2,%3}, {%4,%5,%6,%7}, {%8,%9}, {%0,%1,%2,%3};"
        : "+f"(c0), "+f"(c1), "+f"(c2), "+f"(c3)
        : "r"(a0), "r"(a1), "r"(a2), "r"(a3), "r"(b0), "r"(b1));
}

// ---------------------------------------------------------------------------
// bf16x3 split-precision GEMM with bias (tensor cores, ~fp32 accuracy):
//   C[M,N] = A[M,K] @ W[K,N] + bias[N]
// Block tile 128x128x32, 256 threads = 8 warps (2 m-warps x 4 n-warps),
// warp tile 64x32 = 4 m16-tiles x 4 n8-tiles, mma.m16n8k16.
// Per fp32 input: x = hi(bf16) + lo(bf16); D += Ahi*Bhi + Ahi*Blo + Alo*Bhi.
// smem stores k-adjacent bf16 pairs packed in uint32:
//   As[m][k2]  row stride 20  (20 % 32 == 4  -> frag loads conflict-free)
//   Bs[k2][n]  row stride 136 (136 % 32 == 8 -> frag loads conflict-free)
// Batched over blockIdx.z.
// ---------------------------------------------------------------------------
struct GemmArgs {
    const float* A[3];
    const float* W[3];
    const float* bias[3];
    float*       C[3];
};

#define AS_STRIDE 20
#define BS_STRIDE 136

__global__ __launch_bounds__(256) void gemm_bf16x3_bias_kernel(
    GemmArgs args, int M, int N, int K)
{
    const float* __restrict__ A    = args.A[blockIdx.z];
    const float* __restrict__ W    = args.W[blockIdx.z];
    const float* __restrict__ bias = args.bias[blockIdx.z];
    float*       __restrict__ C    = args.C[blockIdx.z];

    __shared__ uint32_t As_hi[128][AS_STRIDE];
    __shared__ uint32_t As_lo[128][AS_STRIDE];
    __shared__ uint32_t Bs_hi[16][BS_STRIDE];
    __shared__ uint32_t Bs_lo[16][BS_STRIDE];

    const int tid    = threadIdx.x;
    const int lane   = tid & 31;
    const int warpId = tid >> 5;
    const int g      = lane >> 2;       // 0..7
    const int tig    = lane & 3;        // 0..3
    const int warpM  = warpId & 1;      // 0..1 -> m offset 64
    const int warpN  = warpId >> 1;     // 0..3 -> n offset 32
    const int mBase  = blockIdx.y * 128;
    const int nBase  = blockIdx.x * 128;

    float c[4][4][4];                   // [mt][nt][frag]
    #pragma unroll
    for (int mt = 0; mt < 4; mt++)
        #pragma unroll
        for (int nt = 0; nt < 4; nt++)
            #pragma unroll
            for (int r = 0; r < 4; r++) c[mt][nt][r] = 0.f;

    for (int k0 = 0; k0 < K; k0 += 32) {
        // ---- stage A tile (128 x 32): 1024 float4, 4 per thread
        #pragma unroll
        for (int it = 0; it < 4; it++) {
            int f4  = tid + it * 256;
            int row = f4 >> 3;              // 0..127
            int c4  = f4 & 7;               // float4 col 0..7
            float4 v = *reinterpret_cast<const float4*>(
                &A[(size_t)(mBase + row) * K + k0 + c4 * 4]);
            float h0, l0, h1, l1, h2, l2, h3, l3;
            split_hi_lo(v.x, h0, l0); split_hi_lo(v.y, h1, l1);
            split_hi_lo(v.z, h2, l2); split_hi_lo(v.w, h3, l3);
            As_hi[row][c4 * 2 + 0] = pack_bf2(h0, h1);
            As_hi[row][c4 * 2 + 1] = pack_bf2(h2, h3);
            As_lo[row][c4 * 2 + 0] = pack_bf2(l0, l1);
            As_lo[row][c4 * 2 + 1] = pack_bf2(l2, l3);
        }
        // ---- stage W tile (32 x 128) packed along k: 512 row-pairs of float4
        #pragma unroll
        for (int it = 0; it < 2; it++) {
            int p  = tid + it * 256;        // 0..511
            int k2 = p >> 5;                // 0..15
            int n4 = p & 31;                // float4 col 0..31
            const float* w0 = &W[(size_t)(k0 + 2 * k2) * N + nBase + n4 * 4];
            float4 e = *reinterpret_cast<const float4*>(w0);
            float4 o = *reinterpret_cast<const float4*>(w0 + N);
            float he, le, ho, lo_;
            split_hi_lo(e.x, he, le); split_hi_lo(o.x, ho, lo_);
            Bs_hi[k2][n4 * 4 + 0] = pack_bf2(he, ho);
            Bs_lo[k2][n4 * 4 + 0] = pack_bf2(le, lo_);
            split_hi_lo(e.y, he, le); split_hi_lo(o.y, ho, lo_);
            Bs_hi[k2][n4 * 4 + 1] = pack_bf2(he, ho);
            Bs_lo[k2][n4 * 4 + 1] = pack_bf2(le, lo_);
            split_hi_lo(e.z, he, le); split_hi_lo(o.z, ho, lo_);
            Bs_hi[k2][n4 * 4 + 2] = pack_bf2(he, ho);
            Bs_lo[k2][n4 * 4 + 2] = pack_bf2(le, lo_);
            split_hi_lo(e.w, he, le); split_hi_lo(o.w, ho, lo_);
            Bs_hi[k2][n4 * 4 + 3] = pack_bf2(he, ho);
            Bs_lo[k2][n4 * 4 + 3] = pack_bf2(le, lo_);
        }
        __syncthreads();

        // ---- 2 k-steps of 16
        #pragma unroll
        for (int ks = 0; ks < 2; ks++) {
            const int kb = ks * 8;
            uint32_t ah[4][4], al[4][4];
            #pragma unroll
            for (int mt = 0; mt < 4; mt++) {
                const int r0 = warpM * 64 + mt * 16 + g;
                ah[mt][0] = As_hi[r0][kb + tig];
                ah[mt][1] = As_hi[r0 + 8][kb + tig];
                ah[mt][2] = As_hi[r0][kb + tig + 4];
                ah[mt][3] = As_hi[r0 + 8][kb + tig + 4];
                al[mt][0] = As_lo[r0][kb + tig];
                al[mt][1] = As_lo[r0 + 8][kb + tig];
                al[mt][2] = As_lo[r0][kb + tig + 4];
                al[mt][3] = As_lo[r0 + 8][kb + tig + 4];
            }
            uint32_t bh[4][2], bl[4][2];
            #pragma unroll
            for (int nt = 0; nt < 4; nt++) {
                const int cc = warpN * 32 + nt * 8 + g;
                bh[nt][0] = Bs_hi[kb + tig][cc];
                bh[nt][1] = Bs_hi[kb + tig + 4][cc];
                bl[nt][0] = Bs_lo[kb + tig][cc];
                bl[nt][1] = Bs_lo[kb + tig + 4][cc];
            }
            #pragma unroll
            for (int mt = 0; mt < 4; mt++)
                #pragma unroll
                for (int nt = 0; nt < 4; nt++) {
                    mma_bf16(c[mt][nt][0], c[mt][nt][1], c[mt][nt][2], c[mt][nt][3],
                             ah[mt][0], ah[mt][1], ah[mt][2], ah[mt][3],
                             bh[nt][0], bh[nt][1]);
                    mma_bf16(c[mt][nt][0], c[mt][nt][1], c[mt][nt][2], c[mt][nt][3],
                             ah[mt][0], ah[mt][1], ah[mt][2], ah[mt][3],
                             bl[nt][0], bl[nt][1]);
                    mma_bf16(c[mt][nt][0], c[mt][nt][1], c[mt][nt][2], c[mt][nt][3],
                             al[mt][0], al[mt][1], al[mt][2], al[mt][3],
                             bh[nt][0], bh[nt][1]);
                }
        }
        __syncthreads();
    }

    // ---- epilogue: bias + store (float2 per c-pair)
    #pragma unroll
    for (int nt = 0; nt < 4; nt++) {
        const int col = nBase + warpN * 32 + nt * 8 + 2 * tig;
        const float b0 = bias[col];
        const float b1 = bias[col + 1];
        #pragma unroll
        for (int mt = 0; mt < 4; mt++) {
            const int row = mBase + warpM * 64 + mt * 16 + g;
            float2 v0 = make_float2(c[mt][nt][0] + b0, c[mt][nt][1] + b1);
            float2 v1 = make_float2(c[mt][nt][2] + b0, c[mt][nt][3] + b1);
            *reinterpret_cast<float2*>(&C[(size_t)row * N + col])       = v0;
            *reinterpret_cast<float2*>(&C[(size_t)(row + 8) * N + col]) = v1;
        }
    }
}

// ---------------------------------------------------------------------------
// Single-pass causal attention (unchanged from R4; writes unnormalized e,
// row sums to g_l, normalized ctx).
// ---------------------------------------------------------------------------
#define ATTN_SMEM_FLOATS (64*132 + 64*68 + 64*68 + 64*132)

__global__ __launch_bounds__(256, 2) void attn_fused_kernel(
    const float* __restrict__ Qp, const float* __restrict__ Kp,
    const float* __restrict__ Vp, float* __restrict__ attnE,
    float* __restrict__ ctx, float* __restrict__ lsum, int writeAttn)
{
    extern __shared__ float sm[];
    float* Qt = sm;                    // [64][132]  Qt[d][q]
    float* Kt = Qt + 64 * 132;         // [64][68]   Kt[d][k]
    float* Vs = Kt + 64 * 68;          // [64][68]   Vs[k][d]
    float* Pt = Vs + 64 * 68;          // [64][132]  Pt[k][q]

    const int tid = threadIdx.x;
    const int tx = tid & 15;
    const int ty = tid >> 4;
    const int qt = (gridDim.x - 1) - blockIdx.x;
    const int h  = blockIdx.y;
    const int b  = blockIdx.z;
    const int q0 = qt * 128;
    const size_t bS   = (size_t)b * S_LEN;
    const size_t hOff = (size_t)h * HD;

    #pragma unroll
    for (int it = 0; it < 8; it++) {
        int f4 = tid + it * 256;
        int q  = f4 >> 4;
        int dg = (f4 & 15) * 4;
        float4 v = *reinterpret_cast<const float4*>(
            Qp + (bS + q0 + q) * D_MODEL + hOff + dg);
        Qt[(dg + 0) * 132 + q] = v.x;
        Qt[(dg + 1) * 132 + q] = v.y;
        Qt[(dg + 2) * 132 + q] = v.z;
        Qt[(dg + 3) * 132 + q] = v.w;
    }

    float l_run[8];
    float acc[8][4];
    #pragma unroll
    for (int r = 0; r < 8; r++) {
        l_run[r] = 0.f;
        #pragma unroll
        for (int cc = 0; cc < 4; cc++) acc[r][cc] = 0.f;
    }

    const int jtMax = 2 * qt + 1;
    float* ab = attnE + (((size_t)(b * NH + h) * S_LEN + q0) * S_LEN);

    for (int jt = 0; jt <= jtMax; jt++) {
        __syncthreads();
        #pragma unroll
        for (int it = 0; it < 4; it++) {
            int f4 = tid + it * 256;
            int k  = f4 >> 4;
            int dg = (f4 & 15) * 4;
            const size_t rowOff = (bS + jt * 64 + k) * D_MODEL + hOff + dg;
            float4 kv = *reinterpret_cast<const float4*>(Kp + rowOff);
            Kt[(dg + 0) * 68 + k] = kv.x;
            Kt[(dg + 1) * 68 + k] = kv.y;
            Kt[(dg + 2) * 68 + k] = kv.z;
            Kt[(dg + 3) * 68 + k] = kv.w;
            float4 vv = *reinterpret_cast<const float4*>(Vp + rowOff);
            *reinterpret_cast<float4*>(&Vs[k * 68 + dg]) = vv;
        }
        __syncthreads();

        float s[8][4];
        #pragma unroll
        for (int r = 0; r < 8; r++)
            #pragma unroll
            for (int cc = 0; cc < 4; cc++) s[r][cc] = 0.f;

        #pragma unroll 8
        for (int d = 0; d < 64; d++) {
            float4 a0 = *reinterpret_cast<const float4*>(&Qt[d * 132 + ty * 8]);
            float4 a1 = *reinterpret_cast<const float4*>(&Qt[d * 132 + ty * 8 + 4]);
            float4 bk = *reinterpret_cast<const float4*>(&Kt[d * 68 + tx * 4]);
            float a[8] = {a0.x, a0.y, a0.z, a0.w, a1.x, a1.y, a1.z, a1.w};
            #pragma unroll
            for (int r = 0; r < 8; r++) {
                s[r][0] += a[r] * bk.x;
                s[r][1] += a[r] * bk.y;
                s[r][2] += a[r] * bk.z;
                s[r][3] += a[r] * bk.w;
            }
        }

        #pragma unroll
        for (int r = 0; r < 8; r++) {
            const int qi = q0 + ty * 8 + r;
            float le = 0.f;
            #pragma unroll
            for (int cc = 0; cc < 4; cc++) {
                const int kj = jt * 64 + tx * 4 + cc;
                float e = (kj <= qi) ? fast_exp8(s[r][cc]) : 0.f;
                s[r][cc] = e;
                le += e;
            }
            #pragma unroll
            for (int off = 1; off < 16; off <<= 1)
                le += __shfl_xor_sync(0xFFFFFFFFu, le, off);
            l_run[r] += le;
        }

        #pragma unroll
        for (int cc = 0; cc < 4; cc++) {
            float4 p0 = make_float4(s[0][cc], s[1][cc], s[2][cc], s[3][cc]);
            float4 p1 = make_float4(s[4][cc], s[5][cc], s[6][cc], s[7][cc]);
            *reinterpret_cast<float4*>(&Pt[(tx * 4 + cc) * 132 + ty * 8])     = p0;
            *reinterpret_cast<float4*>(&Pt[(tx * 4 + cc) * 132 + ty * 8 + 4]) = p1;
        }
        if (writeAttn) {
            #pragma unroll
            for (int r = 0; r < 8; r++) {
                float4 e4 = make_float4(s[r][0], s[r][1], s[r][2], s[r][3]);
                *reinterpret_cast<float4*>(
                    &ab[(size_t)(ty * 8 + r) * S_LEN + jt * 64 + tx * 4]) = e4;
            }
        }
        __syncthreads();

        #pragma unroll 8
        for (int j = 0; j < 64; j++) {
            float4 p0 = *reinterpret_cast<const float4*>(&Pt[j * 132 + ty * 8]);
            float4 p1 = *reinterpret_cast<const float4*>(&Pt[j * 132 + ty * 8 + 4]);
            float4 vv = *reinterpret_cast<const float4*>(&Vs[j * 68 + tx * 4]);
            float pr[8] = {p0.x, p0.y, p0.z, p0.w, p1.x, p1.y, p1.z, p1.w};
            #pragma unroll
            for (int r = 0; r < 8; r++) {
                acc[r][0] += pr[r] * vv.x;
                acc[r][1] += pr[r] * vv.y;
                acc[r][2] += pr[r] * vv.z;
                acc[r][3] += pr[r] * vv.w;
            }
        }
    }

    #pragma unroll
    for (int r = 0; r < 8; r++) {
        const float inv = 1.0f / l_run[r];
        float4 o;
        o.x = acc[r][0] * inv; o.y = acc[r][1] * inv;
        o.z = acc[r][2] * inv; o.w = acc[r][3] * inv;
        *reinterpret_cast<float4*>(
            ctx + (bS + q0 + ty * 8 + r) * D_MODEL + hOff + tx * 4) = o;
    }
    if (tx == 0) {
        #pragma unroll
        for (int r = 0; r < 8; r++)
            lsum[(size_t)(b * NH + h) * S_LEN + q0 + ty * 8 + r] = l_run[r];
    }
}

// ---------------------------------------------------------------------------
// Normalize attn rows by 1/l and zero-fill the upper triangle.
// ---------------------------------------------------------------------------
__global__ __launch_bounds__(256) void attn_fixup_kernel(
    float* __restrict__ attn, const float* __restrict__ lsum)
{
    const int row = blockIdx.x;
    const int qi  = row & (S_LEN - 1);
    const float inv = 1.0f / lsum[row];
    float* p = attn + (size_t)row * S_LEN;

    #pragma unroll
    for (int it = 0; it < 2; it++) {
        const int j = (threadIdx.x + it * 256) * 4;
        if (j + 3 <= qi) {
            float4 v = *reinterpret_cast<const float4*>(&p[j]);
            v.x *= inv; v.y *= inv; v.z *= inv; v.w *= inv;
            *reinterpret_cast<float4*>(&p[j]) = v;
        } else if (j > qi) {
            *reinterpret_cast<float4*>(&p[j]) = make_float4(0.f, 0.f, 0.f, 0.f);
        } else {
            float4 v = *reinterpret_cast<const float4*>(&p[j]);
            v.x = (j + 0 <= qi) ? v.x * inv : 0.f;
            v.y = (j + 1 <= qi) ? v.y * inv : 0.f;
            v.z = (j + 2 <= qi) ? v.z * inv : 0.f;
            v.w = (j + 3 <= qi) ? v.w * inv : 0.f;
            *reinterpret_cast<float4*>(&p[j]) = v;
        }
    }
}

// ---------------------------------------------------------------------------
extern "C" void kernel_launch(void* const* d_in, const int* in_sizes, int n_in,
                              void* d_out_v, int out_size)
{
    const float* queries = (const float*)d_in[0];
    const float* keys    = (const float*)d_in[1];
    const float* values  = (const float*)d_in[2];
    const float* W_Q = (const float*)d_in[3];
    const float* b_Q = (const float*)d_in[4];
    const float* W_K = (const float*)d_in[5];
    const float* b_K = (const float*)d_in[6];
    const float* W_V = (const float*)d_in[7];
    const float* b_V = (const float*)d_in[8];
    const float* W_O = (const float*)d_in[9];
    const float* b_O = (const float*)d_in[10];
    float* d_out = (float*)d_out_v;

    float *gq, *gk, *gv, *gctx, *gl;
    cudaGetSymbolAddress((void**)&gq,   g_q);
    cudaGetSymbolAddress((void**)&gk,   g_k);
    cudaGetSymbolAddress((void**)&gv,   g_v);
    cudaGetSymbolAddress((void**)&gctx, g_ctx);
    cudaGetSymbolAddress((void**)&gl,   g_l);

    const size_t OUT_E  = (size_t)B_SZ * S_LEN * D_MODEL;          // 8388608
    const size_t ATTN_E = (size_t)B_SZ * NH * S_LEN * S_LEN;       // 268435456
    const size_t osz = (size_t)out_size;

    const int writeAttn = (osz >= ATTN_E) ? 1 : 0;
    const int writeOut  = (osz == OUT_E) || (osz >= OUT_E + ATTN_E);
    float* attn_ptr = d_out + ((osz >= OUT_E + ATTN_E) ? OUT_E : 0);

    GemmArgs qkv;
    qkv.A[0] = queries; qkv.W[0] = W_Q; qkv.bias[0] = b_Q; qkv.C[0] = gq;
    qkv.A[1] = keys;    qkv.W[1] = W_K; qkv.bias[1] = b_K; qkv.C[1] = gk;
    qkv.A[2] = values;  qkv.W[2] = W_V; qkv.bias[2] = b_V; qkv.C[2] = gv;
    dim3 ggrid(D_MODEL / 128, M_ROWS / 128, 3);   // (8, 64, 3)
    gemm_bf16x3_bias_kernel<<<ggrid, 256>>>(qkv, M_ROWS, D_MODEL, D_MODEL);

    const size_t smemBytes = (size_t)ATTN_SMEM_FLOATS * sizeof(float);
    cudaFuncSetAttribute(attn_fused_kernel,
                         cudaFuncAttributeMaxDynamicSharedMemorySize,
                         (int)smemBytes);
    attn_fused_kernel<<<dim3(S_LEN / 128, NH, B_SZ), 256, smemBytes>>>(
        gq, gk, gv, attn_ptr, gctx, gl, writeAttn);

    if (writeAttn)
        attn_fixup_kernel<<<B_SZ * NH * S_LEN, 256>>>(attn_ptr, gl);

    if (writeOut) {
        GemmArgs og;
        og.A[0] = gctx; og.W[0] = W_O; og.bias[0] = b_O; og.C[0] = d_out;
        og.A[1] = og.A[0]; og.W[1] = og.W[0]; og.bias[1] = og.bias[0]; og.C[1] = og.C[0];
        og.A[2] = og.A[0]; og.W[2] = og.W[0]; og.bias[2] = og.bias[0]; og.C[2] = og.C[0];
        dim3 ogrid(D_MODEL / 128, M_ROWS / 128, 1);
        gemm_bf16x3_bias_kernel<<<ogrid, 256>>>(og, M_ROWS, D_MODEL, D_MODEL);
    }
}

// round 6
// speedup vs baseline: 1.4302x; 1.4302x over previous
#include <cuda_runtime.h>
#include <cuda_bf16.h>
#include <cstdint>

#define B_SZ     4
#define S_LEN    2048
#define D_MODEL  1024
#define NH       16
#define HD       64
#define M_ROWS   (B_SZ * S_LEN)          // 8192
#define K2_TOT   (D_MODEL / 2)           // 512

// ---------------- scratch (device globals; no cudaMalloc allowed) ----------
__device__ float g_q[(size_t)M_ROWS * D_MODEL];
__device__ float g_k[(size_t)M_ROWS * D_MODEL];
__device__ float g_v[(size_t)M_ROWS * D_MODEL];
__device__ float g_ctx[(size_t)M_ROWS * D_MODEL];
__device__ float g_l[(size_t)B_SZ * NH * S_LEN];

// packed bf16 pairs (k even/odd in one uint32)
__device__ uint32_t g_in_hi[(size_t)3 * M_ROWS * K2_TOT];
__device__ uint32_t g_in_lo[(size_t)3 * M_ROWS * K2_TOT];
__device__ uint32_t g_w_hi[(size_t)4 * K2_TOT * D_MODEL];
__device__ uint32_t g_w_lo[(size_t)4 * K2_TOT * D_MODEL];
__device__ uint32_t g_ctx_hi[(size_t)M_ROWS * K2_TOT];
__device__ uint32_t g_ctx_lo[(size_t)M_ROWS * K2_TOT];

// ---------------------------------------------------------------------------
// helpers
// ---------------------------------------------------------------------------
__device__ __forceinline__ float fast_exp8(float x)
{
    float t = x * 0.18033688011112042f;            // log2(e)/8
    t = fminf(fmaxf(t, -60.f), 60.f);
    float fi = rintf(t);
    float f  = t - fi;
    float p  = 0.00015403530f;
    p = fmaf(p, f, 0.00133335581f);
    p = fmaf(p, f, 0.00961812911f);
    p = fmaf(p, f, 0.05550410866f);
    p = fmaf(p, f, 0.24022650696f);
    p = fmaf(p, f, 0.69314718056f);
    p = fmaf(p, f, 1.0f);
    int i = (int)fi;
    return p * __int_as_float((i + 127) << 23);
}

__device__ __forceinline__ uint32_t pack_bf2(float a, float b)
{
    __nv_bfloat162 h = __floats2bfloat162_rn(a, b);   // a -> low half
    return *reinterpret_cast<uint32_t*>(&h);
}

__device__ __forceinline__ void split_hi_lo(float x, float& hi, float& lo)
{
    __nv_bfloat16 h = __float2bfloat16(x);
    hi = __bfloat162float(h);
    lo = x - hi;
}

__device__ __forceinline__ void mma_bf16(
    float& c0, float& c1, float& c2, float& c3,
    uint32_t a0, uint32_t a1, uint32_t a2, uint32_t a3,
    uint32_t b0, uint32_t b1)
{
    asm volatile(
        "mma.sync.aligned.m16n8k16.row.col.f32.bf16.bf16.f32 "
        "{%0,%1,%2,%3}, {%4,%5,%6,%7}, {%8,%9}, {%0,%1,%2,%3};"
        : "+f"(c0), "+f"(c1), "+f"(c2), "+f"(c3)
        : "r"(a0), "r"(a1), "r"(a2), "r"(a3), "r"(b0), "r"(b1));
}

// ---------------------------------------------------------------------------
// Split kernels: fp32 -> packed bf16 hi/lo (pairs along contiguous dim)
// ---------------------------------------------------------------------------
struct SplitSrc { const float* src[3]; };

__global__ __launch_bounds__(256) void split_rows_kernel(
    SplitSrc sa, uint2* __restrict__ hi, uint2* __restrict__ lo, size_t f4_per_z)
{
    size_t i = (size_t)blockIdx.x * 256 + threadIdx.x;
    if (i >= f4_per_z) return;
    const float4 v = reinterpret_cast<const float4*>(sa.src[blockIdx.z])[i];
    float h0,l0,h1,l1,h2,l2,h3,l3;
    split_hi_lo(v.x, h0, l0); split_hi_lo(v.y, h1, l1);
    split_hi_lo(v.z, h2, l2); split_hi_lo(v.w, h3, l3);
    const size_t o = (size_t)blockIdx.z * f4_per_z + i;
    hi[o] = make_uint2(pack_bf2(h0, h1), pack_bf2(h2, h3));
    lo[o] = make_uint2(pack_bf2(l0, l1), pack_bf2(l2, l3));
}

struct SplitW { const float* src[4]; };

// W[k][n] (row-major K x N) -> Whi[k2][n] packing rows (2k2, 2k2+1)
__global__ __launch_bounds__(256) void split_w_kernel(
    SplitW sw, uint32_t* __restrict__ hi, uint32_t* __restrict__ lo)
{
    const int p  = blockIdx.x * 256 + threadIdx.x;   // 0 .. K2*N/4-1
    const int k2 = p >> 8;                           // N/4 = 256
    const int n4 = p & 255;
    const float* base = sw.src[blockIdx.z] + (size_t)(2 * k2) * D_MODEL + n4 * 4;
    float4 e = *reinterpret_cast<const float4*>(base);
    float4 o = *reinterpret_cast<const float4*>(base + D_MODEL);
    float he, le, ho, lo_;
    uint4 H, L;
    split_hi_lo(e.x, he, le); split_hi_lo(o.x, ho, lo_);
    H.x = pack_bf2(he, ho);  L.x = pack_bf2(le, lo_);
    split_hi_lo(e.y, he, le); split_hi_lo(o.y, ho, lo_);
    H.y = pack_bf2(he, ho);  L.y = pack_bf2(le, lo_);
    split_hi_lo(e.z, he, le); split_hi_lo(o.z, ho, lo_);
    H.z = pack_bf2(he, ho);  L.z = pack_bf2(le, lo_);
    split_hi_lo(e.w, he, le); split_hi_lo(o.w, ho, lo_);
    H.w = pack_bf2(he, ho);  L.w = pack_bf2(le, lo_);
    const size_t off = (size_t)blockIdx.z * K2_TOT * D_MODEL
                     + (size_t)k2 * D_MODEL + n4 * 4;
    *reinterpret_cast<uint4*>(hi + off) = H;
    *reinterpret_cast<uint4*>(lo + off) = L;
}

// ---------------------------------------------------------------------------
// Packed bf16x3 GEMM with bias: C = A @ W + bias, fp32-accurate.
// Inputs pre-split/packed: Ahi/Alo [M][K2], Whi/Wlo [K2][N].
// Block 128x128x32, double-buffered smem, 8 warps (2m x 4n), warp 64x32,
// mma.m16n8k16 x3 (hi*hi + hi*lo + lo*hi).
// smem: As[m][k2] stride 20 (conflict-free frags);
//       Bt[n][k2] stride 17 (2-way on frags).
// ---------------------------------------------------------------------------
struct PGemmArgs {
    const uint32_t* Ahi[3]; const uint32_t* Alo[3];
    const uint32_t* Whi[3]; const uint32_t* Wlo[3];
    const float* bias[3];
    float*       C[3];
};

#define ASTR 20
#define BSTR 17
#define AS_IDX(b,r,c) ((b)*(128*ASTR) + (r)*ASTR + (c))
#define BT_IDX(b,r,c) ((b)*(128*BSTR) + (r)*BSTR + (c))
#define GEMM_SMEM_WORDS (2*128*ASTR*2 + 2*128*BSTR*2)

__global__ __launch_bounds__(256, 1) void gemm_packed_kernel(
    PGemmArgs args, int M, int N)
{
    const uint32_t* __restrict__ Ahi = args.Ahi[blockIdx.z];
    const uint32_t* __restrict__ Alo = args.Alo[blockIdx.z];
    const uint32_t* __restrict__ Whi = args.Whi[blockIdx.z];
    const uint32_t* __restrict__ Wlo = args.Wlo[blockIdx.z];
    const float*    __restrict__ bias = args.bias[blockIdx.z];
    float*          __restrict__ C    = args.C[blockIdx.z];

    extern __shared__ uint32_t smem[];
    uint32_t* As_hi = smem;                       // [2][128][ASTR]
    uint32_t* As_lo = As_hi + 2 * 128 * ASTR;
    uint32_t* Bt_hi = As_lo + 2 * 128 * ASTR;     // [2][128][BSTR]
    uint32_t* Bt_lo = Bt_hi + 2 * 128 * BSTR;

    const int tid    = threadIdx.x;
    const int lane   = tid & 31;
    const int warpId = tid >> 5;
    const int g      = lane >> 2;       // 0..7
    const int tig    = lane & 3;        // 0..3
    const int warpM  = warpId & 1;
    const int warpN  = warpId >> 1;
    const int mBase  = blockIdx.y * 128;
    const int nBase  = blockIdx.x * 128;

    // staging indices
    const int arow = tid >> 2;          // used as (tid+it*256)>>2
    const int ac4  = tid & 3;
    const int bn4  = tid & 31;

    float c[4][4][4];
    #pragma unroll
    for (int mt = 0; mt < 4; mt++)
        #pragma unroll
        for (int nt = 0; nt < 4; nt++)
            #pragma unroll
            for (int r = 0; r < 4; r++) c[mt][nt][r] = 0.f;

    uint4 ra_h[2], ra_l[2], rb_h[2], rb_l[2];

    auto load_g = [&](int t) {
        #pragma unroll
        for (int it = 0; it < 2; it++) {
            const int row = (tid + it * 256) >> 2;
            const size_t aoff = (size_t)(mBase + row) * K2_TOT + t * 16 + ac4 * 4;
            ra_h[it] = *reinterpret_cast<const uint4*>(Ahi + aoff);
            ra_l[it] = *reinterpret_cast<const uint4*>(Alo + aoff);
            const int k2l = (tid + it * 256) >> 5;
            const size_t boff = (size_t)(t * 16 + k2l) * N + nBase + bn4 * 4;
            rb_h[it] = *reinterpret_cast<const uint4*>(Whi + boff);
            rb_l[it] = *reinterpret_cast<const uint4*>(Wlo + boff);
        }
    };
    auto store_s = [&](int buf) {
        #pragma unroll
        for (int it = 0; it < 2; it++) {
            const int row = (tid + it * 256) >> 2;
            *reinterpret_cast<uint4*>(&As_hi[AS_IDX(buf, row, ac4 * 4)]) = ra_h[it];
            *reinterpret_cast<uint4*>(&As_lo[AS_IDX(buf, row, ac4 * 4)]) = ra_l[it];
            const int k2l = (tid + it * 256) >> 5;
            Bt_hi[BT_IDX(buf, bn4 * 4 + 0, k2l)] = rb_h[it].x;
            Bt_hi[BT_IDX(buf, bn4 * 4 + 1, k2l)] = rb_h[it].y;
            Bt_hi[BT_IDX(buf, bn4 * 4 + 2, k2l)] = rb_h[it].z;
            Bt_hi[BT_IDX(buf, bn4 * 4 + 3, k2l)] = rb_h[it].w;
            Bt_lo[BT_IDX(buf, bn4 * 4 + 0, k2l)] = rb_l[it].x;
            Bt_lo[BT_IDX(buf, bn4 * 4 + 1, k2l)] = rb_l[it].y;
            Bt_lo[BT_IDX(buf, bn4 * 4 + 2, k2l)] = rb_l[it].z;
            Bt_lo[BT_IDX(buf, bn4 * 4 + 3, k2l)] = rb_l[it].w;
        }
    };

    load_g(0);
    store_s(0);
    __syncthreads();

    const int NT = K2_TOT / 16;      // 32 k-blocks of K=32
    int buf = 0;
    #pragma unroll 1
    for (int t = 0; t < NT; t++) {
        if (t + 1 < NT) load_g(t + 1);

        #pragma unroll
        for (int ks = 0; ks < 2; ks++) {
            const int kb = ks * 8;
            uint32_t bh[4][2], bl[4][2];
            #pragma unroll
            for (int nt = 0; nt < 4; nt++) {
                const int cc = warpN * 32 + nt * 8 + g;
                bh[nt][0] = Bt_hi[BT_IDX(buf, cc, kb + tig)];
                bh[nt][1] = Bt_hi[BT_IDX(buf, cc, kb + tig + 4)];
                bl[nt][0] = Bt_lo[BT_IDX(buf, cc, kb + tig)];
                bl[nt][1] = Bt_lo[BT_IDX(buf, cc, kb + tig + 4)];
            }
            #pragma unroll
            for (int mt = 0; mt < 4; mt++) {
                const int r0 = warpM * 64 + mt * 16 + g;
                uint32_t a0 = As_hi[AS_IDX(buf, r0,     kb + tig)];
                uint32_t a1 = As_hi[AS_IDX(buf, r0 + 8, kb + tig)];
                uint32_t a2 = As_hi[AS_IDX(buf, r0,     kb + tig + 4)];
                uint32_t a3 = As_hi[AS_IDX(buf, r0 + 8, kb + tig + 4)];
                uint32_t l0 = As_lo[AS_IDX(buf, r0,     kb + tig)];
                uint32_t l1 = As_lo[AS_IDX(buf, r0 + 8, kb + tig)];
                uint32_t l2 = As_lo[AS_IDX(buf, r0,     kb + tig + 4)];
                uint32_t l3 = As_lo[AS_IDX(buf, r0 + 8, kb + tig + 4)];
                #pragma unroll
                for (int nt = 0; nt < 4; nt++) {
                    mma_bf16(c[mt][nt][0], c[mt][nt][1], c[mt][nt][2], c[mt][nt][3],
                             a0, a1, a2, a3, bh[nt][0], bh[nt][1]);
                    mma_bf16(c[mt][nt][0], c[mt][nt][1], c[mt][nt][2], c[mt][nt][3],
                             a0, a1, a2, a3, bl[nt][0], bl[nt][1]);
                    mma_bf16(c[mt][nt][0], c[mt][nt][1], c[mt][nt][2], c[mt][nt][3],
                             l0, l1, l2, l3, bh[nt][0], bh[nt][1]);
                }
            }
        }

        if (t + 1 < NT) store_s(buf ^ 1);
        __syncthreads();
        buf ^= 1;
    }

    // epilogue: bias + store
    #pragma unroll
    for (int nt = 0; nt < 4; nt++) {
        const int col = nBase + warpN * 32 + nt * 8 + 2 * tig;
        const float b0 = bias[col];
        const float b1 = bias[col + 1];
        #pragma unroll
        for (int mt = 0; mt < 4; mt++) {
            const int row = mBase + warpM * 64 + mt * 16 + g;
            float2 v0 = make_float2(c[mt][nt][0] + b0, c[mt][nt][1] + b1);
            float2 v1 = make_float2(c[mt][nt][2] + b0, c[mt][nt][3] + b1);
            *reinterpret_cast<float2*>(&C[(size_t)row * N + col])       = v0;
            *reinterpret_cast<float2*>(&C[(size_t)(row + 8) * N + col]) = v1;
        }
    }
}

// ---------------------------------------------------------------------------
// Single-pass causal attention (unchanged): unnormalized e to attn buffer,
// row sums to g_l, normalized ctx to g_ctx.
// ---------------------------------------------------------------------------
#define ATTN_SMEM_FLOATS (64*132 + 64*68 + 64*68 + 64*132)

__global__ __launch_bounds__(256, 2) void attn_fused_kernel(
    const float* __restrict__ Qp, const float* __restrict__ Kp,
    const float* __restrict__ Vp, float* __restrict__ attnE,
    float* __restrict__ ctx, float* __restrict__ lsum, int writeAttn)
{
    extern __shared__ float sm[];
    float* Qt = sm;                    // [64][132]  Qt[d][q]
    float* Kt = Qt + 64 * 132;         // [64][68]   Kt[d][k]
    float* Vs = Kt + 64 * 68;          // [64][68]   Vs[k][d]
    float* Pt = Vs + 64 * 68;          // [64][132]  Pt[k][q]

    const int tid = threadIdx.x;
    const int tx = tid & 15;
    const int ty = tid >> 4;
    const int qt = (gridDim.x - 1) - blockIdx.x;
    const int h  = blockIdx.y;
    const int b  = blockIdx.z;
    const int q0 = qt * 128;
    const size_t bS   = (size_t)b * S_LEN;
    const size_t hOff = (size_t)h * HD;

    #pragma unroll
    for (int it = 0; it < 8; it++) {
        int f4 = tid + it * 256;
        int q  = f4 >> 4;
        int dg = (f4 & 15) * 4;
        float4 v = *reinterpret_cast<const float4*>(
            Qp + (bS + q0 + q) * D_MODEL + hOff + dg);
        Qt[(dg + 0) * 132 + q] = v.x;
        Qt[(dg + 1) * 132 + q] = v.y;
        Qt[(dg + 2) * 132 + q] = v.z;
        Qt[(dg + 3) * 132 + q] = v.w;
    }

    float l_run[8];
    float acc[8][4];
    #pragma unroll
    for (int r = 0; r < 8; r++) {
        l_run[r] = 0.f;
        #pragma unroll
        for (int cc = 0; cc < 4; cc++) acc[r][cc] = 0.f;
    }

    const int jtMax = 2 * qt + 1;
    float* ab = attnE + (((size_t)(b * NH + h) * S_LEN + q0) * S_LEN);

    for (int jt = 0; jt <= jtMax; jt++) {
        __syncthreads();
        #pragma unroll
        for (int it = 0; it < 4; it++) {
            int f4 = tid + it * 256;
            int k  = f4 >> 4;
            int dg = (f4 & 15) * 4;
            const size_t rowOff = (bS + jt * 64 + k) * D_MODEL + hOff + dg;
            float4 kv = *reinterpret_cast<const float4*>(Kp + rowOff);
            Kt[(dg + 0) * 68 + k] = kv.x;
            Kt[(dg + 1) * 68 + k] = kv.y;
            Kt[(dg + 2) * 68 + k] = kv.z;
            Kt[(dg + 3) * 68 + k] = kv.w;
            float4 vv = *reinterpret_cast<const float4*>(Vp + rowOff);
            *reinterpret_cast<float4*>(&Vs[k * 68 + dg]) = vv;
        }
        __syncthreads();

        float s[8][4];
        #pragma unroll
        for (int r = 0; r < 8; r++)
            #pragma unroll
            for (int cc = 0; cc < 4; cc++) s[r][cc] = 0.f;

        #pragma unroll 8
        for (int d = 0; d < 64; d++) {
            float4 a0 = *reinterpret_cast<const float4*>(&Qt[d * 132 + ty * 8]);
            float4 a1 = *reinterpret_cast<const float4*>(&Qt[d * 132 + ty * 8 + 4]);
            float4 bk = *reinterpret_cast<const float4*>(&Kt[d * 68 + tx * 4]);
            float a[8] = {a0.x, a0.y, a0.z, a0.w, a1.x, a1.y, a1.z, a1.w};
            #pragma unroll
            for (int r = 0; r < 8; r++) {
                s[r][0] += a[r] * bk.x;
                s[r][1] += a[r] * bk.y;
                s[r][2] += a[r] * bk.z;
                s[r][3] += a[r] * bk.w;
            }
        }

        #pragma unroll
        for (int r = 0; r < 8; r++) {
            const int qi = q0 + ty * 8 + r;
            float le = 0.f;
            #pragma unroll
            for (int cc = 0; cc < 4; cc++) {
                const int kj = jt * 64 + tx * 4 + cc;
                float e = (kj <= qi) ? fast_exp8(s[r][cc]) : 0.f;
                s[r][cc] = e;
                le += e;
            }
            #pragma unroll
            for (int off = 1; off < 16; off <<= 1)
                le += __shfl_xor_sync(0xFFFFFFFFu, le, off);
            l_run[r] += le;
        }

        #pragma unroll
        for (int cc = 0; cc < 4; cc++) {
            float4 p0 = make_float4(s[0][cc], s[1][cc], s[2][cc], s[3][cc]);
            float4 p1 = make_float4(s[4][cc], s[5][cc], s[6][cc], s[7][cc]);
            *reinterpret_cast<float4*>(&Pt[(tx * 4 + cc) * 132 + ty * 8])     = p0;
            *reinterpret_cast<float4*>(&Pt[(tx * 4 + cc) * 132 + ty * 8 + 4]) = p1;
        }
        if (writeAttn) {
            #pragma unroll
            for (int r = 0; r < 8; r++) {
                float4 e4 = make_float4(s[r][0], s[r][1], s[r][2], s[r][3]);
                *reinterpret_cast<float4*>(
                    &ab[(size_t)(ty * 8 + r) * S_LEN + jt * 64 + tx * 4]) = e4;
            }
        }
        __syncthreads();

        #pragma unroll 8
        for (int j = 0; j < 64; j++) {
            float4 p0 = *reinterpret_cast<const float4*>(&Pt[j * 132 + ty * 8]);
            float4 p1 = *reinterpret_cast<const float4*>(&Pt[j * 132 + ty * 8 + 4]);
            float4 vv = *reinterpret_cast<const float4*>(&Vs[j * 68 + tx * 4]);
            float pr[8] = {p0.x, p0.y, p0.z, p0.w, p1.x, p1.y, p1.z, p1.w};
            #pragma unroll
            for (int r = 0; r < 8; r++) {
                acc[r][0] += pr[r] * vv.x;
                acc[r][1] += pr[r] * vv.y;
                acc[r][2] += pr[r] * vv.z;
                acc[r][3] += pr[r] * vv.w;
            }
        }
    }

    #pragma unroll
    for (int r = 0; r < 8; r++) {
        const float inv = 1.0f / l_run[r];
        float4 o;
        o.x = acc[r][0] * inv; o.y = acc[r][1] * inv;
        o.z = acc[r][2] * inv; o.w = acc[r][3] * inv;
        *reinterpret_cast<float4*>(
            ctx + (bS + q0 + ty * 8 + r) * D_MODEL + hOff + tx * 4) = o;
    }
    if (tx == 0) {
        #pragma unroll
        for (int r = 0; r < 8; r++)
            lsum[(size_t)(b * NH + h) * S_LEN + q0 + ty * 8 + r] = l_run[r];
    }
}

// ---------------------------------------------------------------------------
// Normalize attn rows by 1/l and zero-fill the upper triangle.
// ---------------------------------------------------------------------------
__global__ __launch_bounds__(256) void attn_fixup_kernel(
    float* __restrict__ attn, const float* __restrict__ lsum)
{
    const int row = blockIdx.x;
    const int qi  = row & (S_LEN - 1);
    const float inv = 1.0f / lsum[row];
    float* p = attn + (size_t)row * S_LEN;

    #pragma unroll
    for (int it = 0; it < 2; it++) {
        const int j = (threadIdx.x + it * 256) * 4;
        if (j + 3 <= qi) {
            float4 v = *reinterpret_cast<const float4*>(&p[j]);
            v.x *= inv; v.y *= inv; v.z *= inv; v.w *= inv;
            *reinterpret_cast<float4*>(&p[j]) = v;
        } else if (j > qi) {
            *reinterpret_cast<float4*>(&p[j]) = make_float4(0.f, 0.f, 0.f, 0.f);
        } else {
            float4 v = *reinterpret_cast<const float4*>(&p[j]);
            v.x = (j + 0 <= qi) ? v.x * inv : 0.f;
            v.y = (j + 1 <= qi) ? v.y * inv : 0.f;
            v.z = (j + 2 <= qi) ? v.z * inv : 0.f;
            v.w = (j + 3 <= qi) ? v.w * inv : 0.f;
            *reinterpret_cast<float4*>(&p[j]) = v;
        }
    }
}

// ---------------------------------------------------------------------------
extern "C" void kernel_launch(void* const* d_in, const int* in_sizes, int n_in,
                              void* d_out_v, int out_size)
{
    const float* queries = (const float*)d_in[0];
    const float* keys    = (const float*)d_in[1];
    const float* values  = (const float*)d_in[2];
    const float* W_Q = (const float*)d_in[3];
    const float* b_Q = (const float*)d_in[4];
    const float* W_K = (const float*)d_in[5];
    const float* b_K = (const float*)d_in[6];
    const float* W_V = (const float*)d_in[7];
    const float* b_V = (const float*)d_in[8];
    const float* W_O = (const float*)d_in[9];
    const float* b_O = (const float*)d_in[10];
    float* d_out = (float*)d_out_v;

    float *gq, *gk, *gv, *gctx, *gl;
    uint32_t *inhi, *inlo, *whi, *wlo, *chi, *clo;
    cudaGetSymbolAddress((void**)&gq,   g_q);
    cudaGetSymbolAddress((void**)&gk,   g_k);
    cudaGetSymbolAddress((void**)&gv,   g_v);
    cudaGetSymbolAddress((void**)&gctx, g_ctx);
    cudaGetSymbolAddress((void**)&gl,   g_l);
    cudaGetSymbolAddress((void**)&inhi, g_in_hi);
    cudaGetSymbolAddress((void**)&inlo, g_in_lo);
    cudaGetSymbolAddress((void**)&whi,  g_w_hi);
    cudaGetSymbolAddress((void**)&wlo,  g_w_lo);
    cudaGetSymbolAddress((void**)&chi,  g_ctx_hi);
    cudaGetSymbolAddress((void**)&clo,  g_ctx_lo);

    const size_t OUT_E  = (size_t)B_SZ * S_LEN * D_MODEL;          // 8388608
    const size_t ATTN_E = (size_t)B_SZ * NH * S_LEN * S_LEN;       // 268435456
    const size_t osz = (size_t)out_size;

    const int writeAttn = (osz >= ATTN_E) ? 1 : 0;
    const int writeOut  = (osz == OUT_E) || (osz >= OUT_E + ATTN_E);
    float* attn_ptr = d_out + ((osz >= OUT_E + ATTN_E) ? OUT_E : 0);

    const size_t MK2 = (size_t)M_ROWS * K2_TOT;          // 8192*512
    const size_t WK2 = (size_t)K2_TOT * D_MODEL;         // 512*1024

    // ---- split weights (4) and inputs (3)
    SplitW sw;
    sw.src[0] = W_Q; sw.src[1] = W_K; sw.src[2] = W_V; sw.src[3] = W_O;
    split_w_kernel<<<dim3((K2_TOT * D_MODEL / 4) / 256, 1, 4), 256>>>(sw, whi, wlo);

    SplitSrc si;
    si.src[0] = queries; si.src[1] = keys; si.src[2] = values;
    const size_t f4_per_z = (size_t)M_ROWS * D_MODEL / 4;   // 2097152
    split_rows_kernel<<<dim3((unsigned)(f4_per_z / 256), 1, 3), 256>>>(
        si, (uint2*)inhi, (uint2*)inlo, f4_per_z);

    // ---- QKV projection (packed bf16x3 tensor-core GEMM)
    const size_t gemmSmem = (size_t)GEMM_SMEM_WORDS * 4;    // ~74 KB
    cudaFuncSetAttribute(gemm_packed_kernel,
                         cudaFuncAttributeMaxDynamicSharedMemorySize, (int)gemmSmem);

    PGemmArgs qkv;
    qkv.Ahi[0] = inhi;           qkv.Alo[0] = inlo;
    qkv.Ahi[1] = inhi + MK2;     qkv.Alo[1] = inlo + MK2;
    qkv.Ahi[2] = inhi + 2 * MK2; qkv.Alo[2] = inlo + 2 * MK2;
    qkv.Whi[0] = whi;            qkv.Wlo[0] = wlo;
    qkv.Whi[1] = whi + WK2;      qkv.Wlo[1] = wlo + WK2;
    qkv.Whi[2] = whi + 2 * WK2;  qkv.Wlo[2] = wlo + 2 * WK2;
    qkv.bias[0] = b_Q; qkv.bias[1] = b_K; qkv.bias[2] = b_V;
    qkv.C[0] = gq; qkv.C[1] = gk; qkv.C[2] = gv;
    gemm_packed_kernel<<<dim3(D_MODEL / 128, M_ROWS / 128, 3), 256, gemmSmem>>>(
        qkv, M_ROWS, D_MODEL);

    // ---- attention
    const size_t attnSmem = (size_t)ATTN_SMEM_FLOATS * sizeof(float);
    cudaFuncSetAttribute(attn_fused_kernel,
                         cudaFuncAttributeMaxDynamicSharedMemorySize, (int)attnSmem);
    attn_fused_kernel<<<dim3(S_LEN / 128, NH, B_SZ), 256, attnSmem>>>(
        gq, gk, gv, attn_ptr, gctx, gl, writeAttn);

    if (writeAttn)
        attn_fixup_kernel<<<B_SZ * NH * S_LEN, 256>>>(attn_ptr, gl);

    // ---- output projection
    if (writeOut) {
        SplitSrc sc;
        sc.src[0] = gctx; sc.src[1] = gctx; sc.src[2] = gctx;
        split_rows_kernel<<<dim3((unsigned)(f4_per_z / 256), 1, 1), 256>>>(
            sc, (uint2*)chi, (uint2*)clo, f4_per_z);

        PGemmArgs og;
        og.Ahi[0] = chi;           og.Alo[0] = clo;
        og.Whi[0] = whi + 3 * WK2; og.Wlo[0] = wlo + 3 * WK2;
        og.bias[0] = b_O;
        og.C[0] = d_out;
        og.Ahi[1] = og.Ahi[0]; og.Alo[1] = og.Alo[0];
        og.Whi[1] = og.Whi[0]; og.Wlo[1] = og.Wlo[0];
        og.bias[1] = og.bias[0]; og.C[1] = og.C[0];
        og.Ahi[2] = og.Ahi[0]; og.Alo[2] = og.Alo[0];
        og.Whi[2] = og.Whi[0]; og.Wlo[2] = og.Wlo[0];
        og.bias[2] = og.bias[0]; og.C[2] = og.C[0];
        gemm_packed_kernel<<<dim3(D_MODEL / 128, M_ROWS / 128, 1), 256, gemmSmem>>>(
            og, M_ROWS, D_MODEL);
    }
}

// round 7
// speedup vs baseline: 1.8286x; 1.2785x over previous
#include <cuda_runtime.h>
#include <cuda_bf16.h>
#include <cstdint>

#define B_SZ     4
#define S_LEN    2048
#define D_MODEL  1024
#define NH       16
#define HD       64
#define M_ROWS   (B_SZ * S_LEN)          // 8192
#define K2_TOT   (D_MODEL / 2)           // 512
#define MPZ      ((size_t)M_ROWS * K2_TOT)

// ---------------- scratch (device globals; no cudaMalloc allowed) ----------
__device__ float g_l[(size_t)B_SZ * NH * S_LEN];

// packed bf16 pairs (contiguous-dim even/odd in one uint32)
__device__ uint32_t g_in_hi[3 * MPZ];
__device__ uint32_t g_in_lo[3 * MPZ];
__device__ uint32_t g_w_hi[(size_t)4 * K2_TOT * D_MODEL];
__device__ uint32_t g_w_lo[(size_t)4 * K2_TOT * D_MODEL];
__device__ uint32_t g_qkv_hi[3 * MPZ];   // projected q(0.125-scaled),k,v
__device__ uint32_t g_qkv_lo[3 * MPZ];
__device__ uint32_t g_ctx_hi[MPZ];
__device__ uint32_t g_ctx_lo[MPZ];

// ---------------------------------------------------------------------------
// helpers
// ---------------------------------------------------------------------------
__device__ __forceinline__ float fast_exp(float x)
{
    float t = x * 1.4426950408889634f;     // log2(e)
    t = fminf(fmaxf(t, -60.f), 60.f);
    float fi = rintf(t);
    float f  = t - fi;
    float p  = 0.00015403530f;
    p = fmaf(p, f, 0.00133335581f);
    p = fmaf(p, f, 0.00961812911f);
    p = fmaf(p, f, 0.05550410866f);
    p = fmaf(p, f, 0.24022650696f);
    p = fmaf(p, f, 0.69314718056f);
    p = fmaf(p, f, 1.0f);
    int i = (int)fi;
    return p * __int_as_float((i + 127) << 23);
}

__device__ __forceinline__ uint32_t pack_bf2(float a, float b)
{
    __nv_bfloat162 h = __floats2bfloat162_rn(a, b);   // a -> low half
    return *reinterpret_cast<uint32_t*>(&h);
}

__device__ __forceinline__ void split_hi_lo(float x, float& hi, float& lo)
{
    __nv_bfloat16 h = __float2bfloat16(x);
    hi = __bfloat162float(h);
    lo = x - hi;
}

__device__ __forceinline__ void mma_bf16(
    float* c, uint32_t a0, uint32_t a1, uint32_t a2, uint32_t a3,
    uint32_t b0, uint32_t b1)
{
    asm volatile(
        "mma.sync.aligned.m16n8k16.row.col.f32.bf16.bf16.f32 "
        "{%0,%1,%2,%3}, {%4,%5,%6,%7}, {%8,%9}, {%0,%1,%2,%3};"
        : "+f"(c[0]), "+f"(c[1]), "+f"(c[2]), "+f"(c[3])
        : "r"(a0), "r"(a1), "r"(a2), "r"(a3), "r"(b0), "r"(b1));
}

// ---------------------------------------------------------------------------
// Split kernels: fp32 -> packed bf16 hi/lo
// ---------------------------------------------------------------------------
struct SplitSrc { const float* src[3]; };

__global__ __launch_bounds__(256) void split_rows_kernel(
    SplitSrc sa, uint2* __restrict__ hi, uint2* __restrict__ lo, size_t f4_per_z)
{
    size_t i = (size_t)blockIdx.x * 256 + threadIdx.x;
    if (i >= f4_per_z) return;
    const float4 v = reinterpret_cast<const float4*>(sa.src[blockIdx.z])[i];
    float h0,l0,h1,l1,h2,l2,h3,l3;
    split_hi_lo(v.x, h0, l0); split_hi_lo(v.y, h1, l1);
    split_hi_lo(v.z, h2, l2); split_hi_lo(v.w, h3, l3);
    const size_t o = (size_t)blockIdx.z * f4_per_z + i;
    hi[o] = make_uint2(pack_bf2(h0, h1), pack_bf2(h2, h3));
    lo[o] = make_uint2(pack_bf2(l0, l1), pack_bf2(l2, l3));
}

struct SplitW { const float* src[4]; };

__global__ __launch_bounds__(256) void split_w_kernel(
    SplitW sw, uint32_t* __restrict__ hi, uint32_t* __restrict__ lo)
{
    const int p  = blockIdx.x * 256 + threadIdx.x;
    const int k2 = p >> 8;
    const int n4 = p & 255;
    const float* base = sw.src[blockIdx.z] + (size_t)(2 * k2) * D_MODEL + n4 * 4;
    float4 e = *reinterpret_cast<const float4*>(base);
    float4 o = *reinterpret_cast<const float4*>(base + D_MODEL);
    float he, le, ho, lo_;
    uint4 H, L;
    split_hi_lo(e.x, he, le); split_hi_lo(o.x, ho, lo_);
    H.x = pack_bf2(he, ho);  L.x = pack_bf2(le, lo_);
    split_hi_lo(e.y, he, le); split_hi_lo(o.y, ho, lo_);
    H.y = pack_bf2(he, ho);  L.y = pack_bf2(le, lo_);
    split_hi_lo(e.z, he, le); split_hi_lo(o.z, ho, lo_);
    H.z = pack_bf2(he, ho);  L.z = pack_bf2(le, lo_);
    split_hi_lo(e.w, he, le); split_hi_lo(o.w, ho, lo_);
    H.w = pack_bf2(he, ho);  L.w = pack_bf2(le, lo_);
    const size_t off = (size_t)blockIdx.z * K2_TOT * D_MODEL
                     + (size_t)k2 * D_MODEL + n4 * 4;
    *reinterpret_cast<uint4*>(hi + off) = H;
    *reinterpret_cast<uint4*>(lo + off) = L;
}

// ---------------------------------------------------------------------------
// Packed bf16x3 GEMM: C = A @ W + bias.
// MODE 0: fp32 C out.  MODE 1: packed bf16 hi/lo out, scaled (for QKV).
// ---------------------------------------------------------------------------
struct PGemmArgs {
    const uint32_t* Ahi[3]; const uint32_t* Alo[3];
    const uint32_t* Whi[3]; const uint32_t* Wlo[3];
    const float* bias[3];
    float*       C[3];
    uint32_t*    Chi[3];   uint32_t* Clo[3];
    float        scale[3];
};

#define ASTR 20
#define BSTR 17
#define AS_IDX(b,r,c) ((b)*(128*ASTR) + (r)*ASTR + (c))
#define BT_IDX(b,r,c) ((b)*(128*BSTR) + (r)*BSTR + (c))
#define GEMM_SMEM_WORDS (2*128*ASTR*2 + 2*128*BSTR*2)

template<int MODE>
__global__ __launch_bounds__(256, 1) void gemm_packed_kernel(
    PGemmArgs args, int M, int N)
{
    const uint32_t* __restrict__ Ahi = args.Ahi[blockIdx.z];
    const uint32_t* __restrict__ Alo = args.Alo[blockIdx.z];
    const uint32_t* __restrict__ Whi = args.Whi[blockIdx.z];
    const uint32_t* __restrict__ Wlo = args.Wlo[blockIdx.z];
    const float*    __restrict__ bias = args.bias[blockIdx.z];

    extern __shared__ uint32_t smem[];
    uint32_t* As_hi = smem;
    uint32_t* As_lo = As_hi + 2 * 128 * ASTR;
    uint32_t* Bt_hi = As_lo + 2 * 128 * ASTR;
    uint32_t* Bt_lo = Bt_hi + 2 * 128 * BSTR;

    const int tid    = threadIdx.x;
    const int lane   = tid & 31;
    const int warpId = tid >> 5;
    const int g      = lane >> 2;
    const int tig    = lane & 3;
    const int warpM  = warpId & 1;
    const int warpN  = warpId >> 1;
    const int mBase  = blockIdx.y * 128;
    const int nBase  = blockIdx.x * 128;

    const int ac4  = tid & 3;
    const int bn4  = tid & 31;

    float c[4][4][4];
    #pragma unroll
    for (int mt = 0; mt < 4; mt++)
        #pragma unroll
        for (int nt = 0; nt < 4; nt++)
            #pragma unroll
            for (int r = 0; r < 4; r++) c[mt][nt][r] = 0.f;

    uint4 ra_h[2], ra_l[2], rb_h[2], rb_l[2];

    auto load_g = [&](int t) {
        #pragma unroll
        for (int it = 0; it < 2; it++) {
            const int row = (tid + it * 256) >> 2;
            const size_t aoff = (size_t)(mBase + row) * K2_TOT + t * 16 + ac4 * 4;
            ra_h[it] = *reinterpret_cast<const uint4*>(Ahi + aoff);
            ra_l[it] = *reinterpret_cast<const uint4*>(Alo + aoff);
            const int k2l = (tid + it * 256) >> 5;
            const size_t boff = (size_t)(t * 16 + k2l) * N + nBase + bn4 * 4;
            rb_h[it] = *reinterpret_cast<const uint4*>(Whi + boff);
            rb_l[it] = *reinterpret_cast<const uint4*>(Wlo + boff);
        }
    };
    auto store_s = [&](int buf) {
        #pragma unroll
        for (int it = 0; it < 2; it++) {
            const int row = (tid + it * 256) >> 2;
            *reinterpret_cast<uint4*>(&As_hi[AS_IDX(buf, row, ac4 * 4)]) = ra_h[it];
            *reinterpret_cast<uint4*>(&As_lo[AS_IDX(buf, row, ac4 * 4)]) = ra_l[it];
            const int k2l = (tid + it * 256) >> 5;
            Bt_hi[BT_IDX(buf, bn4 * 4 + 0, k2l)] = rb_h[it].x;
            Bt_hi[BT_IDX(buf, bn4 * 4 + 1, k2l)] = rb_h[it].y;
            Bt_hi[BT_IDX(buf, bn4 * 4 + 2, k2l)] = rb_h[it].z;
            Bt_hi[BT_IDX(buf, bn4 * 4 + 3, k2l)] = rb_h[it].w;
            Bt_lo[BT_IDX(buf, bn4 * 4 + 0, k2l)] = rb_l[it].x;
            Bt_lo[BT_IDX(buf, bn4 * 4 + 1, k2l)] = rb_l[it].y;
            Bt_lo[BT_IDX(buf, bn4 * 4 + 2, k2l)] = rb_l[it].z;
            Bt_lo[BT_IDX(buf, bn4 * 4 + 3, k2l)] = rb_l[it].w;
        }
    };

    load_g(0);
    store_s(0);
    __syncthreads();

    const int NT = K2_TOT / 16;
    int buf = 0;
    #pragma unroll 1
    for (int t = 0; t < NT; t++) {
        if (t + 1 < NT) load_g(t + 1);

        #pragma unroll
        for (int ks = 0; ks < 2; ks++) {
            const int kb = ks * 8;
            uint32_t bh[4][2], bl[4][2];
            #pragma unroll
            for (int nt = 0; nt < 4; nt++) {
                const int cc = warpN * 32 + nt * 8 + g;
                bh[nt][0] = Bt_hi[BT_IDX(buf, cc, kb + tig)];
                bh[nt][1] = Bt_hi[BT_IDX(buf, cc, kb + tig + 4)];
                bl[nt][0] = Bt_lo[BT_IDX(buf, cc, kb + tig)];
                bl[nt][1] = Bt_lo[BT_IDX(buf, cc, kb + tig + 4)];
            }
            #pragma unroll
            for (int mt = 0; mt < 4; mt++) {
                const int r0 = warpM * 64 + mt * 16 + g;
                uint32_t a0 = As_hi[AS_IDX(buf, r0,     kb + tig)];
                uint32_t a1 = As_hi[AS_IDX(buf, r0 + 8, kb + tig)];
                uint32_t a2 = As_hi[AS_IDX(buf, r0,     kb + tig + 4)];
                uint32_t a3 = As_hi[AS_IDX(buf, r0 + 8, kb + tig + 4)];
                uint32_t l0 = As_lo[AS_IDX(buf, r0,     kb + tig)];
                uint32_t l1 = As_lo[AS_IDX(buf, r0 + 8, kb + tig)];
                uint32_t l2 = As_lo[AS_IDX(buf, r0,     kb + tig + 4)];
                uint32_t l3 = As_lo[AS_IDX(buf, r0 + 8, kb + tig + 4)];
                #pragma unroll
                for (int nt = 0; nt < 4; nt++) {
                    mma_bf16(c[mt][nt], a0, a1, a2, a3, bh[nt][0], bh[nt][1]);
                    mma_bf16(c[mt][nt], a0, a1, a2, a3, bl[nt][0], bl[nt][1]);
                    mma_bf16(c[mt][nt], l0, l1, l2, l3, bh[nt][0], bh[nt][1]);
                }
            }
        }

        if (t + 1 < NT) store_s(buf ^ 1);
        __syncthreads();
        buf ^= 1;
    }

    if (MODE == 0) {
        float* __restrict__ C = args.C[blockIdx.z];
        #pragma unroll
        for (int nt = 0; nt < 4; nt++) {
            const int col = nBase + warpN * 32 + nt * 8 + 2 * tig;
            const float b0 = bias[col];
            const float b1 = bias[col + 1];
            #pragma unroll
            for (int mt = 0; mt < 4; mt++) {
                const int row = mBase + warpM * 64 + mt * 16 + g;
                float2 v0 = make_float2(c[mt][nt][0] + b0, c[mt][nt][1] + b1);
                float2 v1 = make_float2(c[mt][nt][2] + b0, c[mt][nt][3] + b1);
                *reinterpret_cast<float2*>(&C[(size_t)row * N + col])       = v0;
                *reinterpret_cast<float2*>(&C[(size_t)(row + 8) * N + col]) = v1;
            }
        }
    } else {
        uint32_t* __restrict__ Chi = args.Chi[blockIdx.z];
        uint32_t* __restrict__ Clo = args.Clo[blockIdx.z];
        const float scl = args.scale[blockIdx.z];
        const int N2 = N >> 1;
        #pragma unroll
        for (int nt = 0; nt < 4; nt++) {
            const int col = nBase + warpN * 32 + nt * 8 + 2 * tig;
            const int col2 = col >> 1;
            const float b0 = bias[col];
            const float b1 = bias[col + 1];
            #pragma unroll
            for (int mt = 0; mt < 4; mt++) {
                const int row = mBase + warpM * 64 + mt * 16 + g;
                float v0 = (c[mt][nt][0] + b0) * scl;
                float v1 = (c[mt][nt][1] + b1) * scl;
                float v2 = (c[mt][nt][2] + b0) * scl;
                float v3 = (c[mt][nt][3] + b1) * scl;
                __nv_bfloat162 hA = __floats2bfloat162_rn(v0, v1);
                __nv_bfloat162 hB = __floats2bfloat162_rn(v2, v3);
                Chi[(size_t)row * N2 + col2]       = *reinterpret_cast<uint32_t*>(&hA);
                Chi[(size_t)(row + 8) * N2 + col2] = *reinterpret_cast<uint32_t*>(&hB);
                Clo[(size_t)row * N2 + col2] =
                    pack_bf2(v0 - __bfloat162float(hA.x), v1 - __bfloat162float(hA.y));
                Clo[(size_t)(row + 8) * N2 + col2] =
                    pack_bf2(v2 - __bfloat162float(hB.x), v3 - __bfloat162float(hB.y));
            }
        }
    }
}

// ---------------------------------------------------------------------------
// Tensor-core causal attention. Block = 128 q of one (b,h); key tiles of 64.
// 8 warps: warpM = warpId&3 (32 q each), warpN = warpId>>2 (32 k each).
// QK^T and P@V via mma.m16n8k16 bf16 hi/lo x3; P stays in registers
// (QK C-fragment layout == PV A-fragment layout).
// Writes unnormalized e to attn buffer, row sums to lsum,
// normalized ctx packed bf16 hi/lo to Ch/Cl.
// ---------------------------------------------------------------------------
#define ATTN_SMEM_WORDS (2*128*36 + 4*64*36)   // 18432 words = 72 KB

__global__ __launch_bounds__(256, 1) void attn_mma_kernel(
    const uint32_t* __restrict__ Qh, const uint32_t* __restrict__ Ql,
    const uint32_t* __restrict__ Kh, const uint32_t* __restrict__ Kl,
    const uint32_t* __restrict__ Vh, const uint32_t* __restrict__ Vl,
    float* __restrict__ attnE, uint32_t* __restrict__ Ch, uint32_t* __restrict__ Cl,
    float* __restrict__ lsum, int writeAttn)
{
    extern __shared__ uint32_t sm[];
    uint32_t* Qp_h = sm;                       // [128][36]
    uint32_t* Qp_l = Qp_h + 128 * 36;
    uint32_t* Kp_h = Qp_l + 128 * 36;          // [64][36]
    uint32_t* Kp_l = Kp_h + 64 * 36;
    uint32_t* Vt_h = Kp_l + 64 * 36;           // [64][36]  Vt[d][k2]
    uint32_t* Vt_l = Vt_h + 64 * 36;
    float* red  = reinterpret_cast<float*>(sm);     // epilogue alias [128][64]
    float* lred = reinterpret_cast<float*>(Kp_h);   // epilogue alias [2][128]

    const int tid    = threadIdx.x;
    const int lane   = tid & 31;
    const int warpId = tid >> 5;
    const int g      = lane >> 2;
    const int tig    = lane & 3;
    const int warpM  = warpId & 3;
    const int warpN  = warpId >> 2;
    const int qt = (gridDim.x - 1) - blockIdx.x;   // heavy blocks first
    const int h  = blockIdx.y;
    const int b  = blockIdx.z;
    const int q0 = qt * 128;
    const size_t bS = (size_t)b * S_LEN;
    const int hOff2 = h * (HD / 2);

    // ---- stage Q (packed, pre-scaled by 0.125)
    #pragma unroll
    for (int it = 0; it < 16; it++) {
        int idx = tid + it * 256;
        int q = idx >> 5, d2 = idx & 31;
        size_t off = (bS + q0 + q) * (size_t)K2_TOT + hOff2 + d2;
        Qp_h[q * 36 + d2] = Qh[off];
        Qp_l[q * 36 + d2] = Ql[off];
    }

    float ctx[2][8][4];
    float lpart[2][2];
    #pragma unroll
    for (int mt = 0; mt < 2; mt++) {
        lpart[mt][0] = 0.f; lpart[mt][1] = 0.f;
        #pragma unroll
        for (int nt = 0; nt < 8; nt++)
            #pragma unroll
            for (int r = 0; r < 4; r++) ctx[mt][nt][r] = 0.f;
    }

    float* ab = attnE + (size_t)(b * NH + h) * S_LEN * S_LEN;
    const int jtMax = 2 * qt + 1;

    for (int jt = 0; jt <= jtMax; jt++) {
        __syncthreads();
        // ---- stage K tile (64 x 32 words)
        #pragma unroll
        for (int it = 0; it < 8; it++) {
            int idx = tid + it * 256;
            int k = idx >> 5, d2 = idx & 31;
            size_t off = (bS + jt * 64 + k) * (size_t)K2_TOT + hOff2 + d2;
            Kp_h[k * 36 + d2] = Kh[off];
            Kp_l[k * 36 + d2] = Kl[off];
        }
        // ---- stage V transposed: Vt[d][k2] pairs along k via byte_perm
        #pragma unroll
        for (int it = 0; it < 4; it++) {
            int idx = tid + it * 256;
            int k2 = idx >> 5, d2 = idx & 31;
            size_t off = (bS + jt * 64 + 2 * k2) * (size_t)K2_TOT + hOff2 + d2;
            uint32_t a0 = Vh[off], a1 = Vh[off + K2_TOT];
            Vt_h[(2 * d2) * 36 + k2]     = __byte_perm(a0, a1, 0x5410);
            Vt_h[(2 * d2 + 1) * 36 + k2] = __byte_perm(a0, a1, 0x7632);
            uint32_t b0 = Vl[off], b1 = Vl[off + K2_TOT];
            Vt_l[(2 * d2) * 36 + k2]     = __byte_perm(b0, b1, 0x5410);
            Vt_l[(2 * d2 + 1) * 36 + k2] = __byte_perm(b0, b1, 0x7632);
        }
        __syncthreads();

        // ---- QK^T: sc[mt][nt][4]
        float sc[2][4][4];
        #pragma unroll
        for (int mt = 0; mt < 2; mt++)
            #pragma unroll
            for (int nt = 0; nt < 4; nt++)
                #pragma unroll
                for (int r = 0; r < 4; r++) sc[mt][nt][r] = 0.f;

        #pragma unroll
        for (int ks = 0; ks < 4; ks++) {
            uint32_t ah[2][4], al[2][4];
            #pragma unroll
            for (int mt = 0; mt < 2; mt++) {
                const int r0 = warpM * 32 + mt * 16 + g;
                ah[mt][0] = Qp_h[r0 * 36 + ks * 8 + tig];
                ah[mt][1] = Qp_h[(r0 + 8) * 36 + ks * 8 + tig];
                ah[mt][2] = Qp_h[r0 * 36 + ks * 8 + tig + 4];
                ah[mt][3] = Qp_h[(r0 + 8) * 36 + ks * 8 + tig + 4];
                al[mt][0] = Qp_l[r0 * 36 + ks * 8 + tig];
                al[mt][1] = Qp_l[(r0 + 8) * 36 + ks * 8 + tig];
                al[mt][2] = Qp_l[r0 * 36 + ks * 8 + tig + 4];
                al[mt][3] = Qp_l[(r0 + 8) * 36 + ks * 8 + tig + 4];
            }
            #pragma unroll
            for (int nt = 0; nt < 4; nt++) {
                const int kc = warpN * 32 + nt * 8 + g;
                uint32_t bh0 = Kp_h[kc * 36 + ks * 8 + tig];
                uint32_t bh1 = Kp_h[kc * 36 + ks * 8 + tig + 4];
                uint32_t bl0 = Kp_l[kc * 36 + ks * 8 + tig];
                uint32_t bl1 = Kp_l[kc * 36 + ks * 8 + tig + 4];
                #pragma unroll
                for (int mt = 0; mt < 2; mt++) {
                    mma_bf16(sc[mt][nt], ah[mt][0], ah[mt][1], ah[mt][2], ah[mt][3], bh0, bh1);
                    mma_bf16(sc[mt][nt], ah[mt][0], ah[mt][1], ah[mt][2], ah[mt][3], bl0, bl1);
                    mma_bf16(sc[mt][nt], al[mt][0], al[mt][1], al[mt][2], al[mt][3], bh0, bh1);
                }
            }
        }

        // ---- mask + exp + attn store + l + pack P (registers)
        uint32_t pah[2][2][4], pal[2][2][4];
        #pragma unroll
        for (int mt = 0; mt < 2; mt++) {
            const int rloc = warpM * 32 + mt * 16 + g;
            const int qiA = q0 + rloc;
            const int qiB = qiA + 8;
            #pragma unroll
            for (int nt = 0; nt < 4; nt++) {
                const int kj = jt * 64 + warpN * 32 + nt * 8 + 2 * tig;
                float e0 = (kj     <= qiA) ? fast_exp(sc[mt][nt][0]) : 0.f;
                float e1 = (kj + 1 <= qiA) ? fast_exp(sc[mt][nt][1]) : 0.f;
                float e2 = (kj     <= qiB) ? fast_exp(sc[mt][nt][2]) : 0.f;
                float e3 = (kj + 1 <= qiB) ? fast_exp(sc[mt][nt][3]) : 0.f;
                lpart[mt][0] += e0 + e1;
                lpart[mt][1] += e2 + e3;
                if (writeAttn) {
                    *reinterpret_cast<float2*>(
                        &ab[(size_t)(q0 + rloc) * S_LEN + kj]) = make_float2(e0, e1);
                    *reinterpret_cast<float2*>(
                        &ab[(size_t)(q0 + rloc + 8) * S_LEN + kj]) = make_float2(e2, e3);
                }
                const int ks = nt >> 1;
                const int hw = (nt & 1) * 2;
                __nv_bfloat162 hA = __floats2bfloat162_rn(e0, e1);
                __nv_bfloat162 hB = __floats2bfloat162_rn(e2, e3);
                pah[mt][ks][hw]     = *reinterpret_cast<uint32_t*>(&hA);
                pah[mt][ks][hw + 1] = *reinterpret_cast<uint32_t*>(&hB);
                pal[mt][ks][hw]     = pack_bf2(e0 - __bfloat162float(hA.x),
                                               e1 - __bfloat162float(hA.y));
                pal[mt][ks][hw + 1] = pack_bf2(e2 - __bfloat162float(hB.x),
                                               e3 - __bfloat162float(hB.y));
            }
        }

        // ---- P @ V (warp's 32-k slice)
        #pragma unroll
        for (int ks = 0; ks < 2; ks++) {
            #pragma unroll
            for (int nt = 0; nt < 8; nt++) {
                const int drow = nt * 8 + g;
                const int k2g  = warpN * 16 + ks * 8 + tig;
                uint32_t bh0 = Vt_h[drow * 36 + k2g];
                uint32_t bh1 = Vt_h[drow * 36 + k2g + 4];
                uint32_t bl0 = Vt_l[drow * 36 + k2g];
                uint32_t bl1 = Vt_l[drow * 36 + k2g + 4];
                #pragma unroll
                for (int mt = 0; mt < 2; mt++) {
                    mma_bf16(ctx[mt][nt], pah[mt][ks][0], pah[mt][ks][1],
                             pah[mt][ks][2], pah[mt][ks][3], bh0, bh1);
                    mma_bf16(ctx[mt][nt], pah[mt][ks][0], pah[mt][ks][1],
                             pah[mt][ks][2], pah[mt][ks][3], bl0, bl1);
                    mma_bf16(ctx[mt][nt], pal[mt][ks][0], pal[mt][ks][1],
                             pal[mt][ks][2], pal[mt][ks][3], bh0, bh1);
                }
            }
        }
    }

    // =================== epilogue ===================
    __syncthreads();   // all smem reads done; aliases safe now

    // row-sum l across tig lanes, write per-warpN partial
    #pragma unroll
    for (int mt = 0; mt < 2; mt++) {
        float s0 = lpart[mt][0], s1 = lpart[mt][1];
        s0 += __shfl_xor_sync(0xFFFFFFFFu, s0, 1);
        s0 += __shfl_xor_sync(0xFFFFFFFFu, s0, 2);
        s1 += __shfl_xor_sync(0xFFFFFFFFu, s1, 1);
        s1 += __shfl_xor_sync(0xFFFFFFFFu, s1, 2);
        if (tig == 0) {
            const int r = warpM * 32 + mt * 16 + g;
            lred[warpN * 128 + r]     = s0;
            lred[warpN * 128 + r + 8] = s1;
        }
    }
    // warpN==1 dumps ctx partials
    if (warpN == 1) {
        #pragma unroll
        for (int mt = 0; mt < 2; mt++) {
            const int r = warpM * 32 + mt * 16 + g;
            #pragma unroll
            for (int nt = 0; nt < 8; nt++) {
                const int d = nt * 8 + 2 * tig;
                *reinterpret_cast<float2*>(&red[r * 64 + d]) =
                    make_float2(ctx[mt][nt][0], ctx[mt][nt][1]);
                *reinterpret_cast<float2*>(&red[(r + 8) * 64 + d]) =
                    make_float2(ctx[mt][nt][2], ctx[mt][nt][3]);
            }
        }
    }
    __syncthreads();

    if (warpN == 0) {
        #pragma unroll
        for (int mt = 0; mt < 2; mt++) {
            const int r = warpM * 32 + mt * 16 + g;
            const float lA = lred[r] + lred[128 + r];
            const float lB = lred[r + 8] + lred[128 + r + 8];
            const float iA = 1.0f / lA;
            const float iB = 1.0f / lB;
            if (tig == 0) {
                lsum[(size_t)(b * NH + h) * S_LEN + q0 + r]     = lA;
                lsum[(size_t)(b * NH + h) * S_LEN + q0 + r + 8] = lB;
            }
            #pragma unroll
            for (int nt = 0; nt < 8; nt++) {
                const int d = nt * 8 + 2 * tig;
                float v0 = (ctx[mt][nt][0] + red[r * 64 + d])           * iA;
                float v1 = (ctx[mt][nt][1] + red[r * 64 + d + 1])       * iA;
                float v2 = (ctx[mt][nt][2] + red[(r + 8) * 64 + d])     * iB;
                float v3 = (ctx[mt][nt][3] + red[(r + 8) * 64 + d + 1]) * iB;
                __nv_bfloat162 hA = __floats2bfloat162_rn(v0, v1);
                __nv_bfloat162 hB = __floats2bfloat162_rn(v2, v3);
                const size_t o0 = (bS + q0 + r) * (size_t)K2_TOT + hOff2 + (d >> 1);
                const size_t o1 = (bS + q0 + r + 8) * (size_t)K2_TOT + hOff2 + (d >> 1);
                Ch[o0] = *reinterpret_cast<uint32_t*>(&hA);
                Ch[o1] = *reinterpret_cast<uint32_t*>(&hB);
                Cl[o0] = pack_bf2(v0 - __bfloat162float(hA.x),
                                  v1 - __bfloat162float(hA.y));
                Cl[o1] = pack_bf2(v2 - __bfloat162float(hB.x),
                                  v3 - __bfloat162float(hB.y));
            }
        }
    }
}

// ---------------------------------------------------------------------------
// Normalize attn rows by 1/l and zero-fill the upper triangle.
// ---------------------------------------------------------------------------
__global__ __launch_bounds__(256) void attn_fixup_kernel(
    float* __restrict__ attn, const float* __restrict__ lsum)
{
    const int row = blockIdx.x;
    const int qi  = row & (S_LEN - 1);
    const float inv = 1.0f / lsum[row];
    float* p = attn + (size_t)row * S_LEN;

    #pragma unroll
    for (int it = 0; it < 2; it++) {
        const int j = (threadIdx.x + it * 256) * 4;
        if (j + 3 <= qi) {
            float4 v = *reinterpret_cast<const float4*>(&p[j]);
            v.x *= inv; v.y *= inv; v.z *= inv; v.w *= inv;
            *reinterpret_cast<float4*>(&p[j]) = v;
        } else if (j > qi) {
            *reinterpret_cast<float4*>(&p[j]) = make_float4(0.f, 0.f, 0.f, 0.f);
        } else {
            float4 v = *reinterpret_cast<const float4*>(&p[j]);
            v.x = (j + 0 <= qi) ? v.x * inv : 0.f;
            v.y = (j + 1 <= qi) ? v.y * inv : 0.f;
            v.z = (j + 2 <= qi) ? v.z * inv : 0.f;
            v.w = (j + 3 <= qi) ? v.w * inv : 0.f;
            *reinterpret_cast<float4*>(&p[j]) = v;
        }
    }
}

// ---------------------------------------------------------------------------
extern "C" void kernel_launch(void* const* d_in, const int* in_sizes, int n_in,
                              void* d_out_v, int out_size)
{
    const float* queries = (const float*)d_in[0];
    const float* keys    = (const float*)d_in[1];
    const float* values  = (const float*)d_in[2];
    const float* W_Q = (const float*)d_in[3];
    const float* b_Q = (const float*)d_in[4];
    const float* W_K = (const float*)d_in[5];
    const float* b_K = (const float*)d_in[6];
    const float* W_V = (const float*)d_in[7];
    const float* b_V = (const float*)d_in[8];
    const float* W_O = (const float*)d_in[9];
    const float* b_O = (const float*)d_in[10];
    float* d_out = (float*)d_out_v;

    float *gl;
    uint32_t *inhi, *inlo, *whi, *wlo, *qkvh, *qkvl, *chi, *clo;
    cudaGetSymbolAddress((void**)&gl,   g_l);
    cudaGetSymbolAddress((void**)&inhi, g_in_hi);
    cudaGetSymbolAddress((void**)&inlo, g_in_lo);
    cudaGetSymbolAddress((void**)&whi,  g_w_hi);
    cudaGetSymbolAddress((void**)&wlo,  g_w_lo);
    cudaGetSymbolAddress((void**)&qkvh, g_qkv_hi);
    cudaGetSymbolAddress((void**)&qkvl, g_qkv_lo);
    cudaGetSymbolAddress((void**)&chi,  g_ctx_hi);
    cudaGetSymbolAddress((void**)&clo,  g_ctx_lo);

    const size_t OUT_E  = (size_t)B_SZ * S_LEN * D_MODEL;          // 8388608
    const size_t ATTN_E = (size_t)B_SZ * NH * S_LEN * S_LEN;       // 268435456
    const size_t osz = (size_t)out_size;

    const int writeAttn = (osz >= ATTN_E) ? 1 : 0;
    const int writeOut  = (osz == OUT_E) || (osz >= OUT_E + ATTN_E);
    float* attn_ptr = d_out + ((osz >= OUT_E + ATTN_E) ? OUT_E : 0);

    const size_t WK2 = (size_t)K2_TOT * D_MODEL;

    // ---- split weights (4) and inputs (3)
    SplitW sw;
    sw.src[0] = W_Q; sw.src[1] = W_K; sw.src[2] = W_V; sw.src[3] = W_O;
    split_w_kernel<<<dim3((K2_TOT * D_MODEL / 4) / 256, 1, 4), 256>>>(sw, whi, wlo);

    SplitSrc si;
    si.src[0] = queries; si.src[1] = keys; si.src[2] = values;
    const size_t f4_per_z = (size_t)M_ROWS * D_MODEL / 4;
    split_rows_kernel<<<dim3((unsigned)(f4_per_z / 256), 1, 3), 256>>>(
        si, (uint2*)inhi, (uint2*)inlo, f4_per_z);

    // ---- QKV projection -> packed bf16 hi/lo (Q pre-scaled by 0.125)
    const size_t gemmSmem = (size_t)GEMM_SMEM_WORDS * 4;
    cudaFuncSetAttribute(gemm_packed_kernel<0>,
                         cudaFuncAttributeMaxDynamicSharedMemorySize, (int)gemmSmem);
    cudaFuncSetAttribute(gemm_packed_kernel<1>,
                         cudaFuncAttributeMaxDynamicSharedMemorySize, (int)gemmSmem);

    PGemmArgs qkv;
    for (int z = 0; z < 3; z++) {
        qkv.Ahi[z] = inhi + z * MPZ;  qkv.Alo[z] = inlo + z * MPZ;
        qkv.Whi[z] = whi + z * WK2;   qkv.Wlo[z] = wlo + z * WK2;
        qkv.Chi[z] = qkvh + z * MPZ;  qkv.Clo[z] = qkvl + z * MPZ;
        qkv.C[z] = nullptr;
    }
    qkv.bias[0] = b_Q; qkv.bias[1] = b_K; qkv.bias[2] = b_V;
    qkv.scale[0] = 0.125f; qkv.scale[1] = 1.0f; qkv.scale[2] = 1.0f;
    gemm_packed_kernel<1><<<dim3(D_MODEL / 128, M_ROWS / 128, 3), 256, gemmSmem>>>(
        qkv, M_ROWS, D_MODEL);

    // ---- attention (tensor cores)
    const size_t attnSmem = (size_t)ATTN_SMEM_WORDS * 4;   // 72 KB
    cudaFuncSetAttribute(attn_mma_kernel,
                         cudaFuncAttributeMaxDynamicSharedMemorySize, (int)attnSmem);
    attn_mma_kernel<<<dim3(S_LEN / 128, NH, B_SZ), 256, attnSmem>>>(
        qkvh, qkvl, qkvh + MPZ, qkvl + MPZ, qkvh + 2 * MPZ, qkvl + 2 * MPZ,
        attn_ptr, chi, clo, gl, writeAttn);

    if (writeAttn)
        attn_fixup_kernel<<<B_SZ * NH * S_LEN, 256>>>(attn_ptr, gl);

    // ---- output projection (packed ctx -> fp32 out)
    if (writeOut) {
        PGemmArgs og;
        for (int z = 0; z < 3; z++) {
            og.Ahi[z] = chi;           og.Alo[z] = clo;
            og.Whi[z] = whi + 3 * WK2; og.Wlo[z] = wlo + 3 * WK2;
            og.bias[z] = b_O;          og.C[z] = d_out;
            og.Chi[z] = nullptr;       og.Clo[z] = nullptr;
            og.scale[z] = 1.0f;
        }
        gemm_packed_kernel<0><<<dim3(D_MODEL / 128, M_ROWS / 128, 1), 256, gemmSmem>>>(
            og, M_ROWS, D_MODEL);
    }
}

// round 8
// speedup vs baseline: 1.9413x; 1.0616x over previous
#include <cuda_runtime.h>
#include <cuda_bf16.h>
#include <cstdint>

#define B_SZ     4
#define S_LEN    2048
#define D_MODEL  1024
#define NH       16
#define HD       64
#define M_ROWS   (B_SZ * S_LEN)          // 8192
#define K2_TOT   (D_MODEL / 2)           // 512
#define MPZ      ((size_t)M_ROWS * K2_TOT)

// ---------------- scratch (device globals; no cudaMalloc allowed) ----------
__device__ float g_l[(size_t)B_SZ * NH * S_LEN];

__device__ uint32_t g_in_hi[3 * MPZ];
__device__ uint32_t g_in_lo[3 * MPZ];
__device__ uint32_t g_w_hi[(size_t)4 * K2_TOT * D_MODEL];
__device__ uint32_t g_w_lo[(size_t)4 * K2_TOT * D_MODEL];
__device__ uint32_t g_qkv_hi[3 * MPZ];   // projected q(0.125-scaled),k,v
__device__ uint32_t g_qkv_lo[3 * MPZ];
__device__ uint32_t g_ctx_hi[MPZ];
__device__ uint32_t g_ctx_lo[MPZ];

// ---------------------------------------------------------------------------
// helpers
// ---------------------------------------------------------------------------
__device__ __forceinline__ float fast_exp(float x)
{
    float t = x * 1.4426950408889634f;     // log2(e)
    t = fminf(fmaxf(t, -60.f), 60.f);
    float fi = rintf(t);
    float f  = t - fi;
    float p  = 0.00015403530f;
    p = fmaf(p, f, 0.00133335581f);
    p = fmaf(p, f, 0.00961812911f);
    p = fmaf(p, f, 0.05550410866f);
    p = fmaf(p, f, 0.24022650696f);
    p = fmaf(p, f, 0.69314718056f);
    p = fmaf(p, f, 1.0f);
    int i = (int)fi;
    return p * __int_as_float((i + 127) << 23);
}

__device__ __forceinline__ uint32_t pack_bf2(float a, float b)
{
    __nv_bfloat162 h = __floats2bfloat162_rn(a, b);   // a -> low half
    return *reinterpret_cast<uint32_t*>(&h);
}

__device__ __forceinline__ void split_hi_lo(float x, float& hi, float& lo)
{
    __nv_bfloat16 h = __float2bfloat16(x);
    hi = __bfloat162float(h);
    lo = x - hi;
}

__device__ __forceinline__ void mma_bf16(
    float* c, uint32_t a0, uint32_t a1, uint32_t a2, uint32_t a3,
    uint32_t b0, uint32_t b1)
{
    asm volatile(
        "mma.sync.aligned.m16n8k16.row.col.f32.bf16.bf16.f32 "
        "{%0,%1,%2,%3}, {%4,%5,%6,%7}, {%8,%9}, {%0,%1,%2,%3};"
        : "+f"(c[0]), "+f"(c[1]), "+f"(c[2]), "+f"(c[3])
        : "r"(a0), "r"(a1), "r"(a2), "r"(a3), "r"(b0), "r"(b1));
}

#define CP_ASYNC16(dst, src) \
    asm volatile("cp.async.cg.shared.global [%0], [%1], 16;" \
                 :: "r"(dst), "l"(src) : "memory")
#define CP_COMMIT() asm volatile("cp.async.commit_group;" ::: "memory")
#define CP_WAIT1()  asm volatile("cp.async.wait_group 1;" ::: "memory")
#define CP_WAIT0()  asm volatile("cp.async.wait_group 0;" ::: "memory")

// ---------------------------------------------------------------------------
// Split kernels: fp32 -> packed bf16 hi/lo
// ---------------------------------------------------------------------------
struct SplitSrc { const float* src[3]; };

__global__ __launch_bounds__(256) void split_rows_kernel(
    SplitSrc sa, uint2* __restrict__ hi, uint2* __restrict__ lo, size_t f4_per_z)
{
    size_t i = (size_t)blockIdx.x * 256 + threadIdx.x;
    if (i >= f4_per_z) return;
    const float4 v = reinterpret_cast<const float4*>(sa.src[blockIdx.z])[i];
    float h0,l0,h1,l1,h2,l2,h3,l3;
    split_hi_lo(v.x, h0, l0); split_hi_lo(v.y, h1, l1);
    split_hi_lo(v.z, h2, l2); split_hi_lo(v.w, h3, l3);
    const size_t o = (size_t)blockIdx.z * f4_per_z + i;
    hi[o] = make_uint2(pack_bf2(h0, h1), pack_bf2(h2, h3));
    lo[o] = make_uint2(pack_bf2(l0, l1), pack_bf2(l2, l3));
}

struct SplitW { const float* src[4]; };

__global__ __launch_bounds__(256) void split_w_kernel(
    SplitW sw, uint32_t* __restrict__ hi, uint32_t* __restrict__ lo)
{
    const int p  = blockIdx.x * 256 + threadIdx.x;
    const int k2 = p >> 8;
    const int n4 = p & 255;
    const float* base = sw.src[blockIdx.z] + (size_t)(2 * k2) * D_MODEL + n4 * 4;
    float4 e = *reinterpret_cast<const float4*>(base);
    float4 o = *reinterpret_cast<const float4*>(base + D_MODEL);
    float he, le, ho, lo_;
    uint4 H, L;
    split_hi_lo(e.x, he, le); split_hi_lo(o.x, ho, lo_);
    H.x = pack_bf2(he, ho);  L.x = pack_bf2(le, lo_);
    split_hi_lo(e.y, he, le); split_hi_lo(o.y, ho, lo_);
    H.y = pack_bf2(he, ho);  L.y = pack_bf2(le, lo_);
    split_hi_lo(e.z, he, le); split_hi_lo(o.z, ho, lo_);
    H.z = pack_bf2(he, ho);  L.z = pack_bf2(le, lo_);
    split_hi_lo(e.w, he, le); split_hi_lo(o.w, ho, lo_);
    H.w = pack_bf2(he, ho);  L.w = pack_bf2(le, lo_);
    const size_t off = (size_t)blockIdx.z * K2_TOT * D_MODEL
                     + (size_t)k2 * D_MODEL + n4 * 4;
    *reinterpret_cast<uint4*>(hi + off) = H;
    *reinterpret_cast<uint4*>(lo + off) = L;
}

// ---------------------------------------------------------------------------
// Packed bf16x3 GEMM: C = A @ W + bias. MODE 0: fp32 out. MODE 1: packed out.
// ---------------------------------------------------------------------------
struct PGemmArgs {
    const uint32_t* Ahi[3]; const uint32_t* Alo[3];
    const uint32_t* Whi[3]; const uint32_t* Wlo[3];
    const float* bias[3];
    float*       C[3];
    uint32_t*    Chi[3];   uint32_t* Clo[3];
    float        scale[3];
};

#define ASTR 20
#define BSTR 17
#define AS_IDX(b,r,c) ((b)*(128*ASTR) + (r)*ASTR + (c))
#define BT_IDX(b,r,c) ((b)*(128*BSTR) + (r)*BSTR + (c))
#define GEMM_SMEM_WORDS (2*128*ASTR*2 + 2*128*BSTR*2)

template<int MODE>
__global__ __launch_bounds__(256, 1) void gemm_packed_kernel(
    PGemmArgs args, int M, int N)
{
    const uint32_t* __restrict__ Ahi = args.Ahi[blockIdx.z];
    const uint32_t* __restrict__ Alo = args.Alo[blockIdx.z];
    const uint32_t* __restrict__ Whi = args.Whi[blockIdx.z];
    const uint32_t* __restrict__ Wlo = args.Wlo[blockIdx.z];
    const float*    __restrict__ bias = args.bias[blockIdx.z];

    extern __shared__ uint32_t smem[];
    uint32_t* As_hi = smem;
    uint32_t* As_lo = As_hi + 2 * 128 * ASTR;
    uint32_t* Bt_hi = As_lo + 2 * 128 * ASTR;
    uint32_t* Bt_lo = Bt_hi + 2 * 128 * BSTR;

    const int tid    = threadIdx.x;
    const int lane   = tid & 31;
    const int warpId = tid >> 5;
    const int g      = lane >> 2;
    const int tig    = lane & 3;
    const int warpM  = warpId & 1;
    const int warpN  = warpId >> 1;
    const int mBase  = blockIdx.y * 128;
    const int nBase  = blockIdx.x * 128;

    const int ac4  = tid & 3;
    const int bn4  = tid & 31;

    float c[4][4][4];
    #pragma unroll
    for (int mt = 0; mt < 4; mt++)
        #pragma unroll
        for (int nt = 0; nt < 4; nt++)
            #pragma unroll
            for (int r = 0; r < 4; r++) c[mt][nt][r] = 0.f;

    uint4 ra_h[2], ra_l[2], rb_h[2], rb_l[2];

    auto load_g = [&](int t) {
        #pragma unroll
        for (int it = 0; it < 2; it++) {
            const int row = (tid + it * 256) >> 2;
            const size_t aoff = (size_t)(mBase + row) * K2_TOT + t * 16 + ac4 * 4;
            ra_h[it] = *reinterpret_cast<const uint4*>(Ahi + aoff);
            ra_l[it] = *reinterpret_cast<const uint4*>(Alo + aoff);
            const int k2l = (tid + it * 256) >> 5;
            const size_t boff = (size_t)(t * 16 + k2l) * N + nBase + bn4 * 4;
            rb_h[it] = *reinterpret_cast<const uint4*>(Whi + boff);
            rb_l[it] = *reinterpret_cast<const uint4*>(Wlo + boff);
        }
    };
    auto store_s = [&](int buf) {
        #pragma unroll
        for (int it = 0; it < 2; it++) {
            const int row = (tid + it * 256) >> 2;
            *reinterpret_cast<uint4*>(&As_hi[AS_IDX(buf, row, ac4 * 4)]) = ra_h[it];
            *reinterpret_cast<uint4*>(&As_lo[AS_IDX(buf, row, ac4 * 4)]) = ra_l[it];
            const int k2l = (tid + it * 256) >> 5;
            Bt_hi[BT_IDX(buf, bn4 * 4 + 0, k2l)] = rb_h[it].x;
            Bt_hi[BT_IDX(buf, bn4 * 4 + 1, k2l)] = rb_h[it].y;
            Bt_hi[BT_IDX(buf, bn4 * 4 + 2, k2l)] = rb_h[it].z;
            Bt_hi[BT_IDX(buf, bn4 * 4 + 3, k2l)] = rb_h[it].w;
            Bt_lo[BT_IDX(buf, bn4 * 4 + 0, k2l)] = rb_l[it].x;
            Bt_lo[BT_IDX(buf, bn4 * 4 + 1, k2l)] = rb_l[it].y;
            Bt_lo[BT_IDX(buf, bn4 * 4 + 2, k2l)] = rb_l[it].z;
            Bt_lo[BT_IDX(buf, bn4 * 4 + 3, k2l)] = rb_l[it].w;
        }
    };

    load_g(0);
    store_s(0);
    __syncthreads();

    const int NT = K2_TOT / 16;
    int buf = 0;
    #pragma unroll 1
    for (int t = 0; t < NT; t++) {
        if (t + 1 < NT) load_g(t + 1);

        #pragma unroll
        for (int ks = 0; ks < 2; ks++) {
            const int kb = ks * 8;
            uint32_t bh[4][2], bl[4][2];
            #pragma unroll
            for (int nt = 0; nt < 4; nt++) {
                const int cc = warpN * 32 + nt * 8 + g;
                bh[nt][0] = Bt_hi[BT_IDX(buf, cc, kb + tig)];
                bh[nt][1] = Bt_hi[BT_IDX(buf, cc, kb + tig + 4)];
                bl[nt][0] = Bt_lo[BT_IDX(buf, cc, kb + tig)];
                bl[nt][1] = Bt_lo[BT_IDX(buf, cc, kb + tig + 4)];
            }
            #pragma unroll
            for (int mt = 0; mt < 4; mt++) {
                const int r0 = warpM * 64 + mt * 16 + g;
                uint32_t a0 = As_hi[AS_IDX(buf, r0,     kb + tig)];
                uint32_t a1 = As_hi[AS_IDX(buf, r0 + 8, kb + tig)];
                uint32_t a2 = As_hi[AS_IDX(buf, r0,     kb + tig + 4)];
                uint32_t a3 = As_hi[AS_IDX(buf, r0 + 8, kb + tig + 4)];
                uint32_t l0 = As_lo[AS_IDX(buf, r0,     kb + tig)];
                uint32_t l1 = As_lo[AS_IDX(buf, r0 + 8, kb + tig)];
                uint32_t l2 = As_lo[AS_IDX(buf, r0,     kb + tig + 4)];
                uint32_t l3 = As_lo[AS_IDX(buf, r0 + 8, kb + tig + 4)];
                #pragma unroll
                for (int nt = 0; nt < 4; nt++) {
                    mma_bf16(c[mt][nt], a0, a1, a2, a3, bh[nt][0], bh[nt][1]);
                    mma_bf16(c[mt][nt], a0, a1, a2, a3, bl[nt][0], bl[nt][1]);
                    mma_bf16(c[mt][nt], l0, l1, l2, l3, bh[nt][0], bh[nt][1]);
                }
            }
        }

        if (t + 1 < NT) store_s(buf ^ 1);
        __syncthreads();
        buf ^= 1;
    }

    if (MODE == 0) {
        float* __restrict__ C = args.C[blockIdx.z];
        #pragma unroll
        for (int nt = 0; nt < 4; nt++) {
            const int col = nBase + warpN * 32 + nt * 8 + 2 * tig;
            const float b0 = bias[col];
            const float b1 = bias[col + 1];
            #pragma unroll
            for (int mt = 0; mt < 4; mt++) {
                const int row = mBase + warpM * 64 + mt * 16 + g;
                float2 v0 = make_float2(c[mt][nt][0] + b0, c[mt][nt][1] + b1);
                float2 v1 = make_float2(c[mt][nt][2] + b0, c[mt][nt][3] + b1);
                *reinterpret_cast<float2*>(&C[(size_t)row * N + col])       = v0;
                *reinterpret_cast<float2*>(&C[(size_t)(row + 8) * N + col]) = v1;
            }
        }
    } else {
        uint32_t* __restrict__ Chi = args.Chi[blockIdx.z];
        uint32_t* __restrict__ Clo = args.Clo[blockIdx.z];
        const float scl = args.scale[blockIdx.z];
        const int N2 = N >> 1;
        #pragma unroll
        for (int nt = 0; nt < 4; nt++) {
            const int col = nBase + warpN * 32 + nt * 8 + 2 * tig;
            const int col2 = col >> 1;
            const float b0 = bias[col];
            const float b1 = bias[col + 1];
            #pragma unroll
            for (int mt = 0; mt < 4; mt++) {
                const int row = mBase + warpM * 64 + mt * 16 + g;
                float v0 = (c[mt][nt][0] + b0) * scl;
                float v1 = (c[mt][nt][1] + b1) * scl;
                float v2 = (c[mt][nt][2] + b0) * scl;
                float v3 = (c[mt][nt][3] + b1) * scl;
                __nv_bfloat162 hA = __floats2bfloat162_rn(v0, v1);
                __nv_bfloat162 hB = __floats2bfloat162_rn(v2, v3);
                Chi[(size_t)row * N2 + col2]       = *reinterpret_cast<uint32_t*>(&hA);
                Chi[(size_t)(row + 8) * N2 + col2] = *reinterpret_cast<uint32_t*>(&hB);
                Clo[(size_t)row * N2 + col2] =
                    pack_bf2(v0 - __bfloat162float(hA.x), v1 - __bfloat162float(hA.y));
                Clo[(size_t)(row + 8) * N2 + col2] =
                    pack_bf2(v2 - __bfloat162float(hB.x), v3 - __bfloat162float(hB.y));
            }
        }
    }
}

// ---------------------------------------------------------------------------
// Tensor-core causal attention, cp.async double-buffered K/V pipeline.
// Block = 128 q of one (b,h); key tiles of 64.
// smem word layout:
//   Qp_h [128][36] @ 0      Qp_l @ 4608
//   Kb_h [2][64][36] @ 9216   Kb_l @ 13824
//   Vb_h [2][64][36] @ 18432  Vb_l @ 23040   (V stored RAW [k][d2])
// V fragment transpose done on the fly with 2xLDS + byte_perm.
// ---------------------------------------------------------------------------
#define Q_OFF_H 0
#define Q_OFF_L 4608
#define K_OFF_H 9216
#define K_OFF_L 13824
#define V_OFF_H 18432
#define V_OFF_L 23040
#define TILE_WORDS (64*36)     // 2304
#define ATTN_SMEM_WORDS 27648  // 108 KB

__global__ __launch_bounds__(256, 1) void attn_mma_kernel(
    const uint32_t* __restrict__ Qh, const uint32_t* __restrict__ Ql,
    const uint32_t* __restrict__ Kh, const uint32_t* __restrict__ Kl,
    const uint32_t* __restrict__ Vh, const uint32_t* __restrict__ Vl,
    float* __restrict__ attnE, uint32_t* __restrict__ Ch, uint32_t* __restrict__ Cl,
    float* __restrict__ lsum, int writeAttn)
{
    extern __shared__ uint32_t sm[];
    const uint32_t sbase = (uint32_t)__cvta_generic_to_shared(sm);
    float* red  = reinterpret_cast<float*>(sm);            // epilogue alias [128][64]
    float* lred = reinterpret_cast<float*>(sm + K_OFF_H);  // epilogue alias [2][128]

    const int tid    = threadIdx.x;
    const int lane   = tid & 31;
    const int warpId = tid >> 5;
    const int g      = lane >> 2;
    const int tig    = lane & 3;
    const int warpM  = warpId & 3;
    const int warpN  = warpId >> 2;
    const int qt = (gridDim.x - 1) - blockIdx.x;   // heavy blocks first
    const int h  = blockIdx.y;
    const int b  = blockIdx.z;
    const int q0 = qt * 128;
    const size_t bS = (size_t)b * S_LEN;
    const int hOff2 = h * (HD / 2);
    const int jtMax = 2 * qt + 1;

    // ---- cp.async stage of one K/V tile (raw V) into buffer bufI
    auto issue_tile = [&](int jt, int bufI) {
        #pragma unroll
        for (int it = 0; it < 2; it++) {
            const int idx = tid + it * 256;
            const int k   = idx >> 3;
            const int w4  = (idx & 7) * 4;
            const size_t off = (bS + jt * 64 + k) * (size_t)K2_TOT + hOff2 + w4;
            const uint32_t so = (uint32_t)(bufI * TILE_WORDS + k * 36 + w4) * 4;
            CP_ASYNC16(sbase + (K_OFF_H * 4) + so, Kh + off);
            CP_ASYNC16(sbase + (K_OFF_L * 4) + so, Kl + off);
            CP_ASYNC16(sbase + (V_OFF_H * 4) + so, Vh + off);
            CP_ASYNC16(sbase + (V_OFF_L * 4) + so, Vl + off);
        }
    };

    issue_tile(0, 0);
    CP_COMMIT();

    // ---- stage Q (regular loads; overlaps with first K/V tile in flight)
    #pragma unroll
    for (int it = 0; it < 16; it++) {
        int idx = tid + it * 256;
        int q = idx >> 5, d2 = idx & 31;
        size_t off = (bS + q0 + q) * (size_t)K2_TOT + hOff2 + d2;
        sm[Q_OFF_H + q * 36 + d2] = Qh[off];
        sm[Q_OFF_L + q * 36 + d2] = Ql[off];
    }

    float ctx[2][8][4];
    float lpart[2][2];
    #pragma unroll
    for (int mt = 0; mt < 2; mt++) {
        lpart[mt][0] = 0.f; lpart[mt][1] = 0.f;
        #pragma unroll
        for (int nt = 0; nt < 8; nt++)
            #pragma unroll
            for (int r = 0; r < 4; r++) ctx[mt][nt][r] = 0.f;
    }

    float* ab = attnE + (size_t)(b * NH + h) * S_LEN * S_LEN;

    #pragma unroll 1
    for (int jt = 0; jt <= jtMax; jt++) {
        const int buf = jt & 1;
        if (jt < jtMax) {
            issue_tile(jt + 1, buf ^ 1);
            CP_COMMIT();
            CP_WAIT1();
        } else {
            CP_WAIT0();
        }
        __syncthreads();

        const uint32_t* KH = sm + K_OFF_H + buf * TILE_WORDS;
        const uint32_t* KL = sm + K_OFF_L + buf * TILE_WORDS;
        const uint32_t* VH = sm + V_OFF_H + buf * TILE_WORDS;
        const uint32_t* VL = sm + V_OFF_L + buf * TILE_WORDS;
        const uint32_t* QH = sm + Q_OFF_H;
        const uint32_t* QL = sm + Q_OFF_L;

        // ---- QK^T: sc[mt][nt][4]
        float sc[2][4][4];
        #pragma unroll
        for (int mt = 0; mt < 2; mt++)
            #pragma unroll
            for (int nt = 0; nt < 4; nt++)
                #pragma unroll
                for (int r = 0; r < 4; r++) sc[mt][nt][r] = 0.f;

        #pragma unroll
        for (int ks = 0; ks < 4; ks++) {
            uint32_t ah[2][4], al[2][4];
            #pragma unroll
            for (int mt = 0; mt < 2; mt++) {
                const int r0 = warpM * 32 + mt * 16 + g;
                ah[mt][0] = QH[r0 * 36 + ks * 8 + tig];
                ah[mt][1] = QH[(r0 + 8) * 36 + ks * 8 + tig];
                ah[mt][2] = QH[r0 * 36 + ks * 8 + tig + 4];
                ah[mt][3] = QH[(r0 + 8) * 36 + ks * 8 + tig + 4];
                al[mt][0] = QL[r0 * 36 + ks * 8 + tig];
                al[mt][1] = QL[(r0 + 8) * 36 + ks * 8 + tig];
                al[mt][2] = QL[r0 * 36 + ks * 8 + tig + 4];
                al[mt][3] = QL[(r0 + 8) * 36 + ks * 8 + tig + 4];
            }
            #pragma unroll
            for (int nt = 0; nt < 4; nt++) {
                const int kc = warpN * 32 + nt * 8 + g;
                uint32_t bh0 = KH[kc * 36 + ks * 8 + tig];
                uint32_t bh1 = KH[kc * 36 + ks * 8 + tig + 4];
                uint32_t bl0 = KL[kc * 36 + ks * 8 + tig];
                uint32_t bl1 = KL[kc * 36 + ks * 8 + tig + 4];
                #pragma unroll
                for (int mt = 0; mt < 2; mt++) {
                    mma_bf16(sc[mt][nt], ah[mt][0], ah[mt][1], ah[mt][2], ah[mt][3], bh0, bh1);
                    mma_bf16(sc[mt][nt], ah[mt][0], ah[mt][1], ah[mt][2], ah[mt][3], bl0, bl1);
                    mma_bf16(sc[mt][nt], al[mt][0], al[mt][1], al[mt][2], al[mt][3], bh0, bh1);
                }
            }
        }

        // ---- mask + exp + attn store + l + pack P (registers)
        uint32_t pah[2][2][4], pal[2][2][4];
        #pragma unroll
        for (int mt = 0; mt < 2; mt++) {
            const int rloc = warpM * 32 + mt * 16 + g;
            const int qiA = q0 + rloc;
            const int qiB = qiA + 8;
            #pragma unroll
            for (int nt = 0; nt < 4; nt++) {
                const int kj = jt * 64 + warpN * 32 + nt * 8 + 2 * tig;
                float e0 = (kj     <= qiA) ? fast_exp(sc[mt][nt][0]) : 0.f;
                float e1 = (kj + 1 <= qiA) ? fast_exp(sc[mt][nt][1]) : 0.f;
                float e2 = (kj     <= qiB) ? fast_exp(sc[mt][nt][2]) : 0.f;
                float e3 = (kj + 1 <= qiB) ? fast_exp(sc[mt][nt][3]) : 0.f;
                lpart[mt][0] += e0 + e1;
                lpart[mt][1] += e2 + e3;
                if (writeAttn) {
                    *reinterpret_cast<float2*>(
                        &ab[(size_t)(q0 + rloc) * S_LEN + kj]) = make_float2(e0, e1);
                    *reinterpret_cast<float2*>(
                        &ab[(size_t)(q0 + rloc + 8) * S_LEN + kj]) = make_float2(e2, e3);
                }
                const int ks = nt >> 1;
                const int hw = (nt & 1) * 2;
                __nv_bfloat162 hA = __floats2bfloat162_rn(e0, e1);
                __nv_bfloat162 hB = __floats2bfloat162_rn(e2, e3);
                pah[mt][ks][hw]     = *reinterpret_cast<uint32_t*>(&hA);
                pah[mt][ks][hw + 1] = *reinterpret_cast<uint32_t*>(&hB);
                pal[mt][ks][hw]     = pack_bf2(e0 - __bfloat162float(hA.x),
                                               e1 - __bfloat162float(hA.y));
                pal[mt][ks][hw + 1] = pack_bf2(e2 - __bfloat162float(hB.x),
                                               e3 - __bfloat162float(hB.y));
            }
        }

        // ---- P @ V (warp's 32-k slice), V fragments built on the fly
        #pragma unroll
        for (int ks = 0; ks < 2; ks++) {
            const int kk0 = 2 * (warpN * 16 + ks * 8 + tig);   // rows for b0
            const int kk1 = kk0 + 8;                           // rows for b1
            #pragma unroll
            for (int nt = 0; nt < 8; nt++) {
                const int d  = nt * 8 + g;
                const int d2 = d >> 1;
                const uint32_t sel = (d & 1) ? 0x7632u : 0x5410u;
                uint32_t bh0 = __byte_perm(VH[kk0 * 36 + d2], VH[(kk0 + 1) * 36 + d2], sel);
                uint32_t bh1 = __byte_perm(VH[kk1 * 36 + d2], VH[(kk1 + 1) * 36 + d2], sel);
                uint32_t bl0 = __byte_perm(VL[kk0 * 36 + d2], VL[(kk0 + 1) * 36 + d2], sel);
                uint32_t bl1 = __byte_perm(VL[kk1 * 36 + d2], VL[(kk1 + 1) * 36 + d2], sel);
                #pragma unroll
                for (int mt = 0; mt < 2; mt++) {
                    mma_bf16(ctx[mt][nt], pah[mt][ks][0], pah[mt][ks][1],
                             pah[mt][ks][2], pah[mt][ks][3], bh0, bh1);
                    mma_bf16(ctx[mt][nt], pah[mt][ks][0], pah[mt][ks][1],
                             pah[mt][ks][2], pah[mt][ks][3], bl0, bl1);
                    mma_bf16(ctx[mt][nt], pal[mt][ks][0], pal[mt][ks][1],
                             pal[mt][ks][2], pal[mt][ks][3], bh0, bh1);
                }
            }
        }
        __syncthreads();   // compute done before next tile overwrites buf^1
    }

    // =================== epilogue ===================
    // row-sum l across tig lanes, write per-warpN partial
    #pragma unroll
    for (int mt = 0; mt < 2; mt++) {
        float s0 = lpart[mt][0], s1 = lpart[mt][1];
        s0 += __shfl_xor_sync(0xFFFFFFFFu, s0, 1);
        s0 += __shfl_xor_sync(0xFFFFFFFFu, s0, 2);
        s1 += __shfl_xor_sync(0xFFFFFFFFu, s1, 1);
        s1 += __shfl_xor_sync(0xFFFFFFFFu, s1, 2);
        if (tig == 0) {
            const int r = warpM * 32 + mt * 16 + g;
            lred[warpN * 128 + r]     = s0;
            lred[warpN * 128 + r + 8] = s1;
        }
    }
    // warpN==1 dumps ctx partials
    if (warpN == 1) {
        #pragma unroll
        for (int mt = 0; mt < 2; mt++) {
            const int r = warpM * 32 + mt * 16 + g;
            #pragma unroll
            for (int nt = 0; nt < 8; nt++) {
                const int d = nt * 8 + 2 * tig;
                *reinterpret_cast<float2*>(&red[r * 64 + d]) =
                    make_float2(ctx[mt][nt][0], ctx[mt][nt][1]);
                *reinterpret_cast<float2*>(&red[(r + 8) * 64 + d]) =
                    make_float2(ctx[mt][nt][2], ctx[mt][nt][3]);
            }
        }
    }
    __syncthreads();

    if (warpN == 0) {
        #pragma unroll
        for (int mt = 0; mt < 2; mt++) {
            const int r = warpM * 32 + mt * 16 + g;
            const float lA = lred[r] + lred[128 + r];
            const float lB = lred[r + 8] + lred[128 + r + 8];
            const float iA = 1.0f / lA;
            const float iB = 1.0f / lB;
            if (tig == 0) {
                lsum[(size_t)(b * NH + h) * S_LEN + q0 + r]     = lA;
                lsum[(size_t)(b * NH + h) * S_LEN + q0 + r + 8] = lB;
            }
            #pragma unroll
            for (int nt = 0; nt < 8; nt++) {
                const int d = nt * 8 + 2 * tig;
                float v0 = (ctx[mt][nt][0] + red[r * 64 + d])           * iA;
                float v1 = (ctx[mt][nt][1] + red[r * 64 + d + 1])       * iA;
                float v2 = (ctx[mt][nt][2] + red[(r + 8) * 64 + d])     * iB;
                float v3 = (ctx[mt][nt][3] + red[(r + 8) * 64 + d + 1]) * iB;
                __nv_bfloat162 hA = __floats2bfloat162_rn(v0, v1);
                __nv_bfloat162 hB = __floats2bfloat162_rn(v2, v3);
                const size_t o0 = (bS + q0 + r) * (size_t)K2_TOT + hOff2 + (d >> 1);
                const size_t o1 = (bS + q0 + r + 8) * (size_t)K2_TOT + hOff2 + (d >> 1);
                Ch[o0] = *reinterpret_cast<uint32_t*>(&hA);
                Ch[o1] = *reinterpret_cast<uint32_t*>(&hB);
                Cl[o0] = pack_bf2(v0 - __bfloat162float(hA.x),
                                  v1 - __bfloat162float(hA.y));
                Cl[o1] = pack_bf2(v2 - __bfloat162float(hB.x),
                                  v3 - __bfloat162float(hB.y));
            }
        }
    }
}

// ---------------------------------------------------------------------------
// Normalize attn rows by 1/l and zero-fill the upper triangle.
// ---------------------------------------------------------------------------
__global__ __launch_bounds__(256) void attn_fixup_kernel(
    float* __restrict__ attn, const float* __restrict__ lsum)
{
    const int row = blockIdx.x;
    const int qi  = row & (S_LEN - 1);
    const float inv = 1.0f / lsum[row];
    float* p = attn + (size_t)row * S_LEN;

    #pragma unroll
    for (int it = 0; it < 2; it++) {
        const int j = (threadIdx.x + it * 256) * 4;
        if (j + 3 <= qi) {
            float4 v = *reinterpret_cast<const float4*>(&p[j]);
            v.x *= inv; v.y *= inv; v.z *= inv; v.w *= inv;
            *reinterpret_cast<float4*>(&p[j]) = v;
        } else if (j > qi) {
            *reinterpret_cast<float4*>(&p[j]) = make_float4(0.f, 0.f, 0.f, 0.f);
        } else {
            float4 v = *reinterpret_cast<const float4*>(&p[j]);
            v.x = (j + 0 <= qi) ? v.x * inv : 0.f;
            v.y = (j + 1 <= qi) ? v.y * inv : 0.f;
            v.z = (j + 2 <= qi) ? v.z * inv : 0.f;
            v.w = (j + 3 <= qi) ? v.w * inv : 0.f;
            *reinterpret_cast<float4*>(&p[j]) = v;
        }
    }
}

// ---------------------------------------------------------------------------
extern "C" void kernel_launch(void* const* d_in, const int* in_sizes, int n_in,
                              void* d_out_v, int out_size)
{
    const float* queries = (const float*)d_in[0];
    const float* keys    = (const float*)d_in[1];
    const float* values  = (const float*)d_in[2];
    const float* W_Q = (const float*)d_in[3];
    const float* b_Q = (const float*)d_in[4];
    const float* W_K = (const float*)d_in[5];
    const float* b_K = (const float*)d_in[6];
    const float* W_V = (const float*)d_in[7];
    const float* b_V = (const float*)d_in[8];
    const float* W_O = (const float*)d_in[9];
    const float* b_O = (const float*)d_in[10];
    float* d_out = (float*)d_out_v;

    float *gl;
    uint32_t *inhi, *inlo, *whi, *wlo, *qkvh, *qkvl, *chi, *clo;
    cudaGetSymbolAddress((void**)&gl,   g_l);
    cudaGetSymbolAddress((void**)&inhi, g_in_hi);
    cudaGetSymbolAddress((void**)&inlo, g_in_lo);
    cudaGetSymbolAddress((void**)&whi,  g_w_hi);
    cudaGetSymbolAddress((void**)&wlo,  g_w_lo);
    cudaGetSymbolAddress((void**)&qkvh, g_qkv_hi);
    cudaGetSymbolAddress((void**)&qkvl, g_qkv_lo);
    cudaGetSymbolAddress((void**)&chi,  g_ctx_hi);
    cudaGetSymbolAddress((void**)&clo,  g_ctx_lo);

    const size_t OUT_E  = (size_t)B_SZ * S_LEN * D_MODEL;          // 8388608
    const size_t ATTN_E = (size_t)B_SZ * NH * S_LEN * S_LEN;       // 268435456
    const size_t osz = (size_t)out_size;

    const int writeAttn = (osz >= ATTN_E) ? 1 : 0;
    const int writeOut  = (osz == OUT_E) || (osz >= OUT_E + ATTN_E);
    float* attn_ptr = d_out + ((osz >= OUT_E + ATTN_E) ? OUT_E : 0);

    const size_t WK2 = (size_t)K2_TOT * D_MODEL;

    // ---- split weights (4) and inputs (3)
    SplitW sw;
    sw.src[0] = W_Q; sw.src[1] = W_K; sw.src[2] = W_V; sw.src[3] = W_O;
    split_w_kernel<<<dim3((K2_TOT * D_MODEL / 4) / 256, 1, 4), 256>>>(sw, whi, wlo);

    SplitSrc si;
    si.src[0] = queries; si.src[1] = keys; si.src[2] = values;
    const size_t f4_per_z = (size_t)M_ROWS * D_MODEL / 4;
    split_rows_kernel<<<dim3((unsigned)(f4_per_z / 256), 1, 3), 256>>>(
        si, (uint2*)inhi, (uint2*)inlo, f4_per_z);

    // ---- QKV projection -> packed bf16 hi/lo (Q pre-scaled by 0.125)
    const size_t gemmSmem = (size_t)GEMM_SMEM_WORDS * 4;
    cudaFuncSetAttribute(gemm_packed_kernel<0>,
                         cudaFuncAttributeMaxDynamicSharedMemorySize, (int)gemmSmem);
    cudaFuncSetAttribute(gemm_packed_kernel<1>,
                         cudaFuncAttributeMaxDynamicSharedMemorySize, (int)gemmSmem);

    PGemmArgs qkv;
    for (int z = 0; z < 3; z++) {
        qkv.Ahi[z] = inhi + z * MPZ;  qkv.Alo[z] = inlo + z * MPZ;
        qkv.Whi[z] = whi + z * WK2;   qkv.Wlo[z] = wlo + z * WK2;
        qkv.Chi[z] = qkvh + z * MPZ;  qkv.Clo[z] = qkvl + z * MPZ;
        qkv.C[z] = nullptr;
    }
    qkv.bias[0] = b_Q; qkv.bias[1] = b_K; qkv.bias[2] = b_V;
    qkv.scale[0] = 0.125f; qkv.scale[1] = 1.0f; qkv.scale[2] = 1.0f;
    gemm_packed_kernel<1><<<dim3(D_MODEL / 128, M_ROWS / 128, 3), 256, gemmSmem>>>(
        qkv, M_ROWS, D_MODEL);

    // ---- attention (tensor cores + cp.async pipeline)
    const size_t attnSmem = (size_t)ATTN_SMEM_WORDS * 4;   // 108 KB
    cudaFuncSetAttribute(attn_mma_kernel,
                         cudaFuncAttributeMaxDynamicSharedMemorySize, (int)attnSmem);
    attn_mma_kernel<<<dim3(S_LEN / 128, NH, B_SZ), 256, attnSmem>>>(
        qkvh, qkvl, qkvh + MPZ, qkvl + MPZ, qkvh + 2 * MPZ, qkvl + 2 * MPZ,
        attn_ptr, chi, clo, gl, writeAttn);

    if (writeAttn)
        attn_fixup_kernel<<<B_SZ * NH * S_LEN, 256>>>(attn_ptr, gl);

    // ---- output projection (packed ctx -> fp32 out)
    if (writeOut) {
        PGemmArgs og;
        for (int z = 0; z < 3; z++) {
            og.Ahi[z] = chi;           og.Alo[z] = clo;
            og.Whi[z] = whi + 3 * WK2; og.Wlo[z] = wlo + 3 * WK2;
            og.bias[z] = b_O;          og.C[z] = d_out;
            og.Chi[z] = nullptr;       og.Clo[z] = nullptr;
            og.scale[z] = 1.0f;
        }
        gemm_packed_kernel<0><<<dim3(D_MODEL / 128, M_ROWS / 128, 1), 256, gemmSmem>>>(
            og, M_ROWS, D_MODEL);
    }
}

// round 9
// speedup vs baseline: 1.9616x; 1.0104x over previous
#include <cuda_runtime.h>
#include <cuda_bf16.h>
#include <cstdint>

#define B_SZ     4
#define S_LEN    2048
#define D_MODEL  1024
#define NH       16
#define HD       64
#define M_ROWS   (B_SZ * S_LEN)          // 8192
#define K2_TOT   (D_MODEL / 2)           // 512
#define MPZ      ((size_t)M_ROWS * K2_TOT)

// ---------------- scratch (device globals; no cudaMalloc allowed) ----------
__device__ float g_l[(size_t)B_SZ * NH * S_LEN];

__device__ uint32_t g_in_hi[3 * MPZ];
__device__ uint32_t g_in_lo[3 * MPZ];
__device__ uint32_t g_w_hi[(size_t)4 * K2_TOT * D_MODEL];
__device__ uint32_t g_w_lo[(size_t)4 * K2_TOT * D_MODEL];
__device__ uint32_t g_qkv_hi[3 * MPZ];   // projected q(0.125-scaled),k,v
__device__ uint32_t g_qkv_lo[3 * MPZ];
__device__ uint32_t g_ctx_hi[MPZ];
__device__ uint32_t g_ctx_lo[MPZ];

// ---------------------------------------------------------------------------
// helpers
// ---------------------------------------------------------------------------
__device__ __forceinline__ float fast_exp(float x)
{
    float t = x * 1.4426950408889634f;     // log2(e)
    t = fminf(fmaxf(t, -60.f), 60.f);
    float fi = rintf(t);
    float f  = t - fi;
    float p  = 0.00015403530f;
    p = fmaf(p, f, 0.00133335581f);
    p = fmaf(p, f, 0.00961812911f);
    p = fmaf(p, f, 0.05550410866f);
    p = fmaf(p, f, 0.24022650696f);
    p = fmaf(p, f, 0.69314718056f);
    p = fmaf(p, f, 1.0f);
    int i = (int)fi;
    return p * __int_as_float((i + 127) << 23);
}

__device__ __forceinline__ uint32_t pack_bf2(float a, float b)
{
    __nv_bfloat162 h = __floats2bfloat162_rn(a, b);   // a -> low half
    return *reinterpret_cast<uint32_t*>(&h);
}

__device__ __forceinline__ void split_hi_lo(float x, float& hi, float& lo)
{
    __nv_bfloat16 h = __float2bfloat16(x);
    hi = __bfloat162float(h);
    lo = x - hi;
}

__device__ __forceinline__ void mma_bf16(
    float* c, uint32_t a0, uint32_t a1, uint32_t a2, uint32_t a3,
    uint32_t b0, uint32_t b1)
{
    asm volatile(
        "mma.sync.aligned.m16n8k16.row.col.f32.bf16.bf16.f32 "
        "{%0,%1,%2,%3}, {%4,%5,%6,%7}, {%8,%9}, {%0,%1,%2,%3};"
        : "+f"(c[0]), "+f"(c[1]), "+f"(c[2]), "+f"(c[3])
        : "r"(a0), "r"(a1), "r"(a2), "r"(a3), "r"(b0), "r"(b1));
}

#define CP_ASYNC16(dst, src) \
    asm volatile("cp.async.cg.shared.global [%0], [%1], 16;" \
                 :: "r"(dst), "l"(src) : "memory")
#define CP_COMMIT() asm volatile("cp.async.commit_group;" ::: "memory")
#define CP_WAIT1()  asm volatile("cp.async.wait_group 1;" ::: "memory")
#define CP_WAIT0()  asm volatile("cp.async.wait_group 0;" ::: "memory")

// ---------------------------------------------------------------------------
// Split kernels: fp32 -> packed bf16 hi/lo
// ---------------------------------------------------------------------------
struct SplitSrc { const float* src[3]; };

__global__ __launch_bounds__(256) void split_rows_kernel(
    SplitSrc sa, uint2* __restrict__ hi, uint2* __restrict__ lo, size_t f4_per_z)
{
    size_t i = (size_t)blockIdx.x * 256 + threadIdx.x;
    if (i >= f4_per_z) return;
    const float4 v = reinterpret_cast<const float4*>(sa.src[blockIdx.z])[i];
    float h0,l0,h1,l1,h2,l2,h3,l3;
    split_hi_lo(v.x, h0, l0); split_hi_lo(v.y, h1, l1);
    split_hi_lo(v.z, h2, l2); split_hi_lo(v.w, h3, l3);
    const size_t o = (size_t)blockIdx.z * f4_per_z + i;
    hi[o] = make_uint2(pack_bf2(h0, h1), pack_bf2(h2, h3));
    lo[o] = make_uint2(pack_bf2(l0, l1), pack_bf2(l2, l3));
}

struct SplitW { const float* src[4]; };

__global__ __launch_bounds__(256) void split_w_kernel(
    SplitW sw, uint32_t* __restrict__ hi, uint32_t* __restrict__ lo)
{
    const int p  = blockIdx.x * 256 + threadIdx.x;
    const int k2 = p >> 8;
    const int n4 = p & 255;
    const float* base = sw.src[blockIdx.z] + (size_t)(2 * k2) * D_MODEL + n4 * 4;
    float4 e = *reinterpret_cast<const float4*>(base);
    float4 o = *reinterpret_cast<const float4*>(base + D_MODEL);
    float he, le, ho, lo_;
    uint4 H, L;
    split_hi_lo(e.x, he, le); split_hi_lo(o.x, ho, lo_);
    H.x = pack_bf2(he, ho);  L.x = pack_bf2(le, lo_);
    split_hi_lo(e.y, he, le); split_hi_lo(o.y, ho, lo_);
    H.y = pack_bf2(he, ho);  L.y = pack_bf2(le, lo_);
    split_hi_lo(e.z, he, le); split_hi_lo(o.z, ho, lo_);
    H.z = pack_bf2(he, ho);  L.z = pack_bf2(le, lo_);
    split_hi_lo(e.w, he, le); split_hi_lo(o.w, ho, lo_);
    H.w = pack_bf2(he, ho);  L.w = pack_bf2(le, lo_);
    const size_t off = (size_t)blockIdx.z * K2_TOT * D_MODEL
                     + (size_t)k2 * D_MODEL + n4 * 4;
    *reinterpret_cast<uint4*>(hi + off) = H;
    *reinterpret_cast<uint4*>(lo + off) = L;
}

// ---------------------------------------------------------------------------
// Packed bf16x3 GEMM: C = A @ W + bias. MODE 0: fp32 out. MODE 1: packed out.
// ---------------------------------------------------------------------------
struct PGemmArgs {
    const uint32_t* Ahi[3]; const uint32_t* Alo[3];
    const uint32_t* Whi[3]; const uint32_t* Wlo[3];
    const float* bias[3];
    float*       C[3];
    uint32_t*    Chi[3];   uint32_t* Clo[3];
    float        scale[3];
};

#define ASTR 20
#define BSTR 17
#define AS_IDX(b,r,c) ((b)*(128*ASTR) + (r)*ASTR + (c))
#define BT_IDX(b,r,c) ((b)*(128*BSTR) + (r)*BSTR + (c))
#define GEMM_SMEM_WORDS (2*128*ASTR*2 + 2*128*BSTR*2)

template<int MODE>
__global__ __launch_bounds__(256, 1) void gemm_packed_kernel(
    PGemmArgs args, int M, int N)
{
    const uint32_t* __restrict__ Ahi = args.Ahi[blockIdx.z];
    const uint32_t* __restrict__ Alo = args.Alo[blockIdx.z];
    const uint32_t* __restrict__ Whi = args.Whi[blockIdx.z];
    const uint32_t* __restrict__ Wlo = args.Wlo[blockIdx.z];
    const float*    __restrict__ bias = args.bias[blockIdx.z];

    extern __shared__ uint32_t smem[];
    uint32_t* As_hi = smem;
    uint32_t* As_lo = As_hi + 2 * 128 * ASTR;
    uint32_t* Bt_hi = As_lo + 2 * 128 * ASTR;
    uint32_t* Bt_lo = Bt_hi + 2 * 128 * BSTR;

    const int tid    = threadIdx.x;
    const int lane   = tid & 31;
    const int warpId = tid >> 5;
    const int g      = lane >> 2;
    const int tig    = lane & 3;
    const int warpM  = warpId & 1;
    const int warpN  = warpId >> 1;
    const int mBase  = blockIdx.y * 128;
    const int nBase  = blockIdx.x * 128;

    const int ac4  = tid & 3;
    const int bn4  = tid & 31;

    float c[4][4][4];
    #pragma unroll
    for (int mt = 0; mt < 4; mt++)
        #pragma unroll
        for (int nt = 0; nt < 4; nt++)
            #pragma unroll
            for (int r = 0; r < 4; r++) c[mt][nt][r] = 0.f;

    uint4 ra_h[2], ra_l[2], rb_h[2], rb_l[2];

    auto load_g = [&](int t) {
        #pragma unroll
        for (int it = 0; it < 2; it++) {
            const int row = (tid + it * 256) >> 2;
            const size_t aoff = (size_t)(mBase + row) * K2_TOT + t * 16 + ac4 * 4;
            ra_h[it] = *reinterpret_cast<const uint4*>(Ahi + aoff);
            ra_l[it] = *reinterpret_cast<const uint4*>(Alo + aoff);
            const int k2l = (tid + it * 256) >> 5;
            const size_t boff = (size_t)(t * 16 + k2l) * N + nBase + bn4 * 4;
            rb_h[it] = *reinterpret_cast<const uint4*>(Whi + boff);
            rb_l[it] = *reinterpret_cast<const uint4*>(Wlo + boff);
        }
    };
    auto store_s = [&](int buf) {
        #pragma unroll
        for (int it = 0; it < 2; it++) {
            const int row = (tid + it * 256) >> 2;
            *reinterpret_cast<uint4*>(&As_hi[AS_IDX(buf, row, ac4 * 4)]) = ra_h[it];
            *reinterpret_cast<uint4*>(&As_lo[AS_IDX(buf, row, ac4 * 4)]) = ra_l[it];
            const int k2l = (tid + it * 256) >> 5;
            Bt_hi[BT_IDX(buf, bn4 * 4 + 0, k2l)] = rb_h[it].x;
            Bt_hi[BT_IDX(buf, bn4 * 4 + 1, k2l)] = rb_h[it].y;
            Bt_hi[BT_IDX(buf, bn4 * 4 + 2, k2l)] = rb_h[it].z;
            Bt_hi[BT_IDX(buf, bn4 * 4 + 3, k2l)] = rb_h[it].w;
            Bt_lo[BT_IDX(buf, bn4 * 4 + 0, k2l)] = rb_l[it].x;
            Bt_lo[BT_IDX(buf, bn4 * 4 + 1, k2l)] = rb_l[it].y;
            Bt_lo[BT_IDX(buf, bn4 * 4 + 2, k2l)] = rb_l[it].z;
            Bt_lo[BT_IDX(buf, bn4 * 4 + 3, k2l)] = rb_l[it].w;
        }
    };

    load_g(0);
    store_s(0);
    __syncthreads();

    const int NT = K2_TOT / 16;
    int buf = 0;
    #pragma unroll 1
    for (int t = 0; t < NT; t++) {
        if (t + 1 < NT) load_g(t + 1);

        #pragma unroll
        for (int ks = 0; ks < 2; ks++) {
            const int kb = ks * 8;
            uint32_t bh[4][2], bl[4][2];
            #pragma unroll
            for (int nt = 0; nt < 4; nt++) {
                const int cc = warpN * 32 + nt * 8 + g;
                bh[nt][0] = Bt_hi[BT_IDX(buf, cc, kb + tig)];
                bh[nt][1] = Bt_hi[BT_IDX(buf, cc, kb + tig + 4)];
                bl[nt][0] = Bt_lo[BT_IDX(buf, cc, kb + tig)];
                bl[nt][1] = Bt_lo[BT_IDX(buf, cc, kb + tig + 4)];
            }
            #pragma unroll
            for (int mt = 0; mt < 4; mt++) {
                const int r0 = warpM * 64 + mt * 16 + g;
                uint32_t a0 = As_hi[AS_IDX(buf, r0,     kb + tig)];
                uint32_t a1 = As_hi[AS_IDX(buf, r0 + 8, kb + tig)];
                uint32_t a2 = As_hi[AS_IDX(buf, r0,     kb + tig + 4)];
                uint32_t a3 = As_hi[AS_IDX(buf, r0 + 8, kb + tig + 4)];
                uint32_t l0 = As_lo[AS_IDX(buf, r0,     kb + tig)];
                uint32_t l1 = As_lo[AS_IDX(buf, r0 + 8, kb + tig)];
                uint32_t l2 = As_lo[AS_IDX(buf, r0,     kb + tig + 4)];
                uint32_t l3 = As_lo[AS_IDX(buf, r0 + 8, kb + tig + 4)];
                #pragma unroll
                for (int nt = 0; nt < 4; nt++) {
                    mma_bf16(c[mt][nt], a0, a1, a2, a3, bh[nt][0], bh[nt][1]);
                    mma_bf16(c[mt][nt], a0, a1, a2, a3, bl[nt][0], bl[nt][1]);
                    mma_bf16(c[mt][nt], l0, l1, l2, l3, bh[nt][0], bh[nt][1]);
                }
            }
        }

        if (t + 1 < NT) store_s(buf ^ 1);
        __syncthreads();
        buf ^= 1;
    }

    if (MODE == 0) {
        float* __restrict__ C = args.C[blockIdx.z];
        #pragma unroll
        for (int nt = 0; nt < 4; nt++) {
            const int col = nBase + warpN * 32 + nt * 8 + 2 * tig;
            const float b0 = bias[col];
            const float b1 = bias[col + 1];
            #pragma unroll
            for (int mt = 0; mt < 4; mt++) {
                const int row = mBase + warpM * 64 + mt * 16 + g;
                float2 v0 = make_float2(c[mt][nt][0] + b0, c[mt][nt][1] + b1);
                float2 v1 = make_float2(c[mt][nt][2] + b0, c[mt][nt][3] + b1);
                *reinterpret_cast<float2*>(&C[(size_t)row * N + col])       = v0;
                *reinterpret_cast<float2*>(&C[(size_t)(row + 8) * N + col]) = v1;
            }
        }
    } else {
        uint32_t* __restrict__ Chi = args.Chi[blockIdx.z];
        uint32_t* __restrict__ Clo = args.Clo[blockIdx.z];
        const float scl = args.scale[blockIdx.z];
        const int N2 = N >> 1;
        #pragma unroll
        for (int nt = 0; nt < 4; nt++) {
            const int col = nBase + warpN * 32 + nt * 8 + 2 * tig;
            const int col2 = col >> 1;
            const float b0 = bias[col];
            const float b1 = bias[col + 1];
            #pragma unroll
            for (int mt = 0; mt < 4; mt++) {
                const int row = mBase + warpM * 64 + mt * 16 + g;
                float v0 = (c[mt][nt][0] + b0) * scl;
                float v1 = (c[mt][nt][1] + b1) * scl;
                float v2 = (c[mt][nt][2] + b0) * scl;
                float v3 = (c[mt][nt][3] + b1) * scl;
                __nv_bfloat162 hA = __floats2bfloat162_rn(v0, v1);
                __nv_bfloat162 hB = __floats2bfloat162_rn(v2, v3);
                Chi[(size_t)row * N2 + col2]       = *reinterpret_cast<uint32_t*>(&hA);
                Chi[(size_t)(row + 8) * N2 + col2] = *reinterpret_cast<uint32_t*>(&hB);
                Clo[(size_t)row * N2 + col2] =
                    pack_bf2(v0 - __bfloat162float(hA.x), v1 - __bfloat162float(hA.y));
                Clo[(size_t)(row + 8) * N2 + col2] =
                    pack_bf2(v2 - __bfloat162float(hB.x), v3 - __bfloat162float(hB.y));
            }
        }
    }
}

// ---------------------------------------------------------------------------
// Tensor-core causal attention, cp.async double-buffered K/V pipeline.
// 512 threads = 16 warps: warpM = warpId&7 (16 q rows), warpN = warpId>>3
// (32 k cols). Block = 128 q of one (b,h); key tiles of 64.
// smem word layout:
//   Qp_h [128][36] @ 0      Qp_l @ 4608
//   Kb_h [2][64][36] @ 9216   Kb_l @ 13824
//   Vb_h [2][64][36] @ 18432  Vb_l @ 23040   (V stored RAW [k][d2])
// V fragment transpose on the fly with 2xLDS + byte_perm.
// ---------------------------------------------------------------------------
#define Q_OFF_H 0
#define Q_OFF_L 4608
#define K_OFF_H 9216
#define K_OFF_L 13824
#define V_OFF_H 18432
#define V_OFF_L 23040
#define TILE_WORDS (64*36)     // 2304
#define ATTN_SMEM_WORDS 27648  // 108 KB

__global__ __launch_bounds__(512, 1) void attn_mma_kernel(
    const uint32_t* __restrict__ Qh, const uint32_t* __restrict__ Ql,
    const uint32_t* __restrict__ Kh, const uint32_t* __restrict__ Kl,
    const uint32_t* __restrict__ Vh, const uint32_t* __restrict__ Vl,
    float* __restrict__ attnE, uint32_t* __restrict__ Ch, uint32_t* __restrict__ Cl,
    float* __restrict__ lsum, int writeAttn)
{
    extern __shared__ uint32_t sm[];
    const uint32_t sbase = (uint32_t)__cvta_generic_to_shared(sm);
    float* red  = reinterpret_cast<float*>(sm);            // epilogue alias [128][64]
    float* lred = reinterpret_cast<float*>(sm + K_OFF_H);  // epilogue alias [2][128]

    const int tid    = threadIdx.x;
    const int lane   = tid & 31;
    const int warpId = tid >> 5;
    const int g      = lane >> 2;
    const int tig    = lane & 3;
    const int warpM  = warpId & 7;     // 0..7 -> 16 q rows each
    const int warpN  = warpId >> 3;    // 0..1 -> 32 k cols each
    const int qt = (gridDim.x - 1) - blockIdx.x;   // heavy blocks first
    const int h  = blockIdx.y;
    const int b  = blockIdx.z;
    const int q0 = qt * 128;
    const size_t bS = (size_t)b * S_LEN;
    const int hOff2 = h * (HD / 2);
    const int jtMax = 2 * qt + 1;

    // ---- cp.async stage of one K/V tile (raw V) into buffer bufI
    auto issue_tile = [&](int jt, int bufI) {
        const int k   = tid >> 3;          // 0..63
        const int w4  = (tid & 7) * 4;     // 0..28
        const size_t off = (bS + jt * 64 + k) * (size_t)K2_TOT + hOff2 + w4;
        const uint32_t so = (uint32_t)(bufI * TILE_WORDS + k * 36 + w4) * 4;
        CP_ASYNC16(sbase + (K_OFF_H * 4) + so, Kh + off);
        CP_ASYNC16(sbase + (K_OFF_L * 4) + so, Kl + off);
        CP_ASYNC16(sbase + (V_OFF_H * 4) + so, Vh + off);
        CP_ASYNC16(sbase + (V_OFF_L * 4) + so, Vl + off);
    };

    issue_tile(0, 0);
    CP_COMMIT();

    // ---- stage Q (regular loads; overlaps with first K/V tile in flight)
    #pragma unroll
    for (int it = 0; it < 8; it++) {
        int idx = tid + it * 512;
        int q = idx >> 5, d2 = idx & 31;
        size_t off = (bS + q0 + q) * (size_t)K2_TOT + hOff2 + d2;
        sm[Q_OFF_H + q * 36 + d2] = Qh[off];
        sm[Q_OFF_L + q * 36 + d2] = Ql[off];
    }

    float ctx[8][4];
    float lpart[2];
    lpart[0] = 0.f; lpart[1] = 0.f;
    #pragma unroll
    for (int nt = 0; nt < 8; nt++)
        #pragma unroll
        for (int r = 0; r < 4; r++) ctx[nt][r] = 0.f;

    float* ab = attnE + (size_t)(b * NH + h) * S_LEN * S_LEN;

    #pragma unroll 1
    for (int jt = 0; jt <= jtMax; jt++) {
        const int buf = jt & 1;
        if (jt < jtMax) {
            issue_tile(jt + 1, buf ^ 1);
            CP_COMMIT();
            CP_WAIT1();
        } else {
            CP_WAIT0();
        }
        __syncthreads();

        const uint32_t* KH = sm + K_OFF_H + buf * TILE_WORDS;
        const uint32_t* KL = sm + K_OFF_L + buf * TILE_WORDS;
        const uint32_t* VH = sm + V_OFF_H + buf * TILE_WORDS;
        const uint32_t* VL = sm + V_OFF_L + buf * TILE_WORDS;
        const uint32_t* QH = sm + Q_OFF_H;
        const uint32_t* QL = sm + Q_OFF_L;

        // ---- QK^T: sc[nt][4] for 16q x 32k
        float sc[4][4];
        #pragma unroll
        for (int nt = 0; nt < 4; nt++)
            #pragma unroll
            for (int r = 0; r < 4; r++) sc[nt][r] = 0.f;

        const int r0 = warpM * 16 + g;
        #pragma unroll
        for (int ks = 0; ks < 4; ks++) {
            uint32_t ah0 = QH[r0 * 36 + ks * 8 + tig];
            uint32_t ah1 = QH[(r0 + 8) * 36 + ks * 8 + tig];
            uint32_t ah2 = QH[r0 * 36 + ks * 8 + tig + 4];
            uint32_t ah3 = QH[(r0 + 8) * 36 + ks * 8 + tig + 4];
            uint32_t al0 = QL[r0 * 36 + ks * 8 + tig];
            uint32_t al1 = QL[(r0 + 8) * 36 + ks * 8 + tig];
            uint32_t al2 = QL[r0 * 36 + ks * 8 + tig + 4];
            uint32_t al3 = QL[(r0 + 8) * 36 + ks * 8 + tig + 4];
            #pragma unroll
            for (int nt = 0; nt < 4; nt++) {
                const int kc = warpN * 32 + nt * 8 + g;
                uint32_t bh0 = KH[kc * 36 + ks * 8 + tig];
                uint32_t bh1 = KH[kc * 36 + ks * 8 + tig + 4];
                uint32_t bl0 = KL[kc * 36 + ks * 8 + tig];
                uint32_t bl1 = KL[kc * 36 + ks * 8 + tig + 4];
                mma_bf16(sc[nt], ah0, ah1, ah2, ah3, bh0, bh1);
                mma_bf16(sc[nt], ah0, ah1, ah2, ah3, bl0, bl1);
                mma_bf16(sc[nt], al0, al1, al2, al3, bh0, bh1);
            }
        }

        // ---- mask + exp + attn store + l + pack P (registers)
        uint32_t pah[2][4], pal[2][4];
        const int qiA = q0 + r0;
        const int qiB = qiA + 8;
        #pragma unroll
        for (int nt = 0; nt < 4; nt++) {
            const int kj = jt * 64 + warpN * 32 + nt * 8 + 2 * tig;
            float e0 = (kj     <= qiA) ? fast_exp(sc[nt][0]) : 0.f;
            float e1 = (kj + 1 <= qiA) ? fast_exp(sc[nt][1]) : 0.f;
            float e2 = (kj     <= qiB) ? fast_exp(sc[nt][2]) : 0.f;
            float e3 = (kj + 1 <= qiB) ? fast_exp(sc[nt][3]) : 0.f;
            lpart[0] += e0 + e1;
            lpart[1] += e2 + e3;
            if (writeAttn) {
                *reinterpret_cast<float2*>(
                    &ab[(size_t)(q0 + r0) * S_LEN + kj]) = make_float2(e0, e1);
                *reinterpret_cast<float2*>(
                    &ab[(size_t)(q0 + r0 + 8) * S_LEN + kj]) = make_float2(e2, e3);
            }
            const int ks = nt >> 1;
            const int hw = (nt & 1) * 2;
            __nv_bfloat162 hA = __floats2bfloat162_rn(e0, e1);
            __nv_bfloat162 hB = __floats2bfloat162_rn(e2, e3);
            pah[ks][hw]     = *reinterpret_cast<uint32_t*>(&hA);
            pah[ks][hw + 1] = *reinterpret_cast<uint32_t*>(&hB);
            pal[ks][hw]     = pack_bf2(e0 - __bfloat162float(hA.x),
                                       e1 - __bfloat162float(hA.y));
            pal[ks][hw + 1] = pack_bf2(e2 - __bfloat162float(hB.x),
                                       e3 - __bfloat162float(hB.y));
        }

        // ---- P @ V (warp's 32-k slice), V fragments built on the fly
        #pragma unroll
        for (int ks = 0; ks < 2; ks++) {
            const int kk0 = 2 * (warpN * 16 + ks * 8 + tig);   // rows for b0
            const int kk1 = kk0 + 8;                           // rows for b1
            #pragma unroll
            for (int nt = 0; nt < 8; nt++) {
                const int d  = nt * 8 + g;
                const int d2 = d >> 1;
                const uint32_t sel = (d & 1) ? 0x7632u : 0x5410u;
                uint32_t bh0 = __byte_perm(VH[kk0 * 36 + d2], VH[(kk0 + 1) * 36 + d2], sel);
                uint32_t bh1 = __byte_perm(VH[kk1 * 36 + d2], VH[(kk1 + 1) * 36 + d2], sel);
                uint32_t bl0 = __byte_perm(VL[kk0 * 36 + d2], VL[(kk0 + 1) * 36 + d2], sel);
                uint32_t bl1 = __byte_perm(VL[kk1 * 36 + d2], VL[(kk1 + 1) * 36 + d2], sel);
                mma_bf16(ctx[nt], pah[ks][0], pah[ks][1], pah[ks][2], pah[ks][3], bh0, bh1);
                mma_bf16(ctx[nt], pah[ks][0], pah[ks][1], pah[ks][2], pah[ks][3], bl0, bl1);
                mma_bf16(ctx[nt], pal[ks][0], pal[ks][1], pal[ks][2], pal[ks][3], bh0, bh1);
            }
        }
        __syncthreads();   // compute done before next tile overwrites buf^1
    }

    // =================== epilogue ===================
    const int r0e = warpM * 16 + g;
    // row-sum l across tig lanes, write per-warpN partial
    {
        float s0 = lpart[0], s1 = lpart[1];
        s0 += __shfl_xor_sync(0xFFFFFFFFu, s0, 1);
        s0 += __shfl_xor_sync(0xFFFFFFFFu, s0, 2);
        s1 += __shfl_xor_sync(0xFFFFFFFFu, s1, 1);
        s1 += __shfl_xor_sync(0xFFFFFFFFu, s1, 2);
        if (tig == 0) {
            lred[warpN * 128 + r0e]     = s0;
            lred[warpN * 128 + r0e + 8] = s1;
        }
    }
    // warpN==1 dumps ctx partials
    if (warpN == 1) {
        #pragma unroll
        for (int nt = 0; nt < 8; nt++) {
            const int d = nt * 8 + 2 * tig;
            *reinterpret_cast<float2*>(&red[r0e * 64 + d]) =
                make_float2(ctx[nt][0], ctx[nt][1]);
            *reinterpret_cast<float2*>(&red[(r0e + 8) * 64 + d]) =
                make_float2(ctx[nt][2], ctx[nt][3]);
        }
    }
    __syncthreads();

    if (warpN == 0) {
        const float lA = lred[r0e] + lred[128 + r0e];
        const float lB = lred[r0e + 8] + lred[128 + r0e + 8];
        const float iA = 1.0f / lA;
        const float iB = 1.0f / lB;
        if (tig == 0) {
            lsum[(size_t)(b * NH + h) * S_LEN + q0 + r0e]     = lA;
            lsum[(size_t)(b * NH + h) * S_LEN + q0 + r0e + 8] = lB;
        }
        #pragma unroll
        for (int nt = 0; nt < 8; nt++) {
            const int d = nt * 8 + 2 * tig;
            float v0 = (ctx[nt][0] + red[r0e * 64 + d])           * iA;
            float v1 = (ctx[nt][1] + red[r0e * 64 + d + 1])       * iA;
            float v2 = (ctx[nt][2] + red[(r0e + 8) * 64 + d])     * iB;
            float v3 = (ctx[nt][3] + red[(r0e + 8) * 64 + d + 1]) * iB;
            __nv_bfloat162 hA = __floats2bfloat162_rn(v0, v1);
            __nv_bfloat162 hB = __floats2bfloat162_rn(v2, v3);
            const size_t o0 = (bS + q0 + r0e) * (size_t)K2_TOT + hOff2 + (d >> 1);
            const size_t o1 = (bS + q0 + r0e + 8) * (size_t)K2_TOT + hOff2 + (d >> 1);
            Ch[o0] = *reinterpret_cast<uint32_t*>(&hA);
            Ch[o1] = *reinterpret_cast<uint32_t*>(&hB);
            Cl[o0] = pack_bf2(v0 - __bfloat162float(hA.x),
                              v1 - __bfloat162float(hA.y));
            Cl[o1] = pack_bf2(v2 - __bfloat162float(hB.x),
                              v3 - __bfloat162float(hB.y));
        }
    }
}

// ---------------------------------------------------------------------------
// Normalize attn rows by 1/l and zero-fill the upper triangle.
// ---------------------------------------------------------------------------
__global__ __launch_bounds__(256) void attn_fixup_kernel(
    float* __restrict__ attn, const float* __restrict__ lsum)
{
    const int row = blockIdx.x;
    const int qi  = row & (S_LEN - 1);
    const float inv = 1.0f / lsum[row];
    float* p = attn + (size_t)row * S_LEN;

    #pragma unroll
    for (int it = 0; it < 2; it++) {
        const int j = (threadIdx.x + it * 256) * 4;
        if (j + 3 <= qi) {
            float4 v = *reinterpret_cast<const float4*>(&p[j]);
            v.x *= inv; v.y *= inv; v.z *= inv; v.w *= inv;
            *reinterpret_cast<float4*>(&p[j]) = v;
        } else if (j > qi) {
            *reinterpret_cast<float4*>(&p[j]) = make_float4(0.f, 0.f, 0.f, 0.f);
        } else {
            float4 v = *reinterpret_cast<const float4*>(&p[j]);
            v.x = (j + 0 <= qi) ? v.x * inv : 0.f;
            v.y = (j + 1 <= qi) ? v.y * inv : 0.f;
            v.z = (j + 2 <= qi) ? v.z * inv : 0.f;
            v.w = (j + 3 <= qi) ? v.w * inv : 0.f;
            *reinterpret_cast<float4*>(&p[j]) = v;
        }
    }
}

// ---------------------------------------------------------------------------
extern "C" void kernel_launch(void* const* d_in, const int* in_sizes, int n_in,
                              void* d_out_v, int out_size)
{
    const float* queries = (const float*)d_in[0];
    const float* keys    = (const float*)d_in[1];
    const float* values  = (const float*)d_in[2];
    const float* W_Q = (const float*)d_in[3];
    const float* b_Q = (const float*)d_in[4];
    const float* W_K = (const float*)d_in[5];
    const float* b_K = (const float*)d_in[6];
    const float* W_V = (const float*)d_in[7];
    const float* b_V = (const float*)d_in[8];
    const float* W_O = (const float*)d_in[9];
    const float* b_O = (const float*)d_in[10];
    float* d_out = (float*)d_out_v;

    float *gl;
    uint32_t *inhi, *inlo, *whi, *wlo, *qkvh, *qkvl, *chi, *clo;
    cudaGetSymbolAddress((void**)&gl,   g_l);
    cudaGetSymbolAddress((void**)&inhi, g_in_hi);
    cudaGetSymbolAddress((void**)&inlo, g_in_lo);
    cudaGetSymbolAddress((void**)&whi,  g_w_hi);
    cudaGetSymbolAddress((void**)&wlo,  g_w_lo);
    cudaGetSymbolAddress((void**)&qkvh, g_qkv_hi);
    cudaGetSymbolAddress((void**)&qkvl, g_qkv_lo);
    cudaGetSymbolAddress((void**)&chi,  g_ctx_hi);
    cudaGetSymbolAddress((void**)&clo,  g_ctx_lo);

    const size_t OUT_E  = (size_t)B_SZ * S_LEN * D_MODEL;          // 8388608
    const size_t ATTN_E = (size_t)B_SZ * NH * S_LEN * S_LEN;       // 268435456
    const size_t osz = (size_t)out_size;

    const int writeAttn = (osz >= ATTN_E) ? 1 : 0;
    const int writeOut  = (osz == OUT_E) || (osz >= OUT_E + ATTN_E);
    float* attn_ptr = d_out + ((osz >= OUT_E + ATTN_E) ? OUT_E : 0);

    const size_t WK2 = (size_t)K2_TOT * D_MODEL;

    // ---- split weights (4) and inputs (3)
    SplitW sw;
    sw.src[0] = W_Q; sw.src[1] = W_K; sw.src[2] = W_V; sw.src[3] = W_O;
    split_w_kernel<<<dim3((K2_TOT * D_MODEL / 4) / 256, 1, 4), 256>>>(sw, whi, wlo);

    SplitSrc si;
    si.src[0] = queries; si.src[1] = keys; si.src[2] = values;
    const size_t f4_per_z = (size_t)M_ROWS * D_MODEL / 4;
    split_rows_kernel<<<dim3((unsigned)(f4_per_z / 256), 1, 3), 256>>>(
        si, (uint2*)inhi, (uint2*)inlo, f4_per_z);

    // ---- QKV projection -> packed bf16 hi/lo (Q pre-scaled by 0.125)
    const size_t gemmSmem = (size_t)GEMM_SMEM_WORDS * 4;
    cudaFuncSetAttribute(gemm_packed_kernel<0>,
                         cudaFuncAttributeMaxDynamicSharedMemorySize, (int)gemmSmem);
    cudaFuncSetAttribute(gemm_packed_kernel<1>,
                         cudaFuncAttributeMaxDynamicSharedMemorySize, (int)gemmSmem);

    PGemmArgs qkv;
    for (int z = 0; z < 3; z++) {
        qkv.Ahi[z] = inhi + z * MPZ;  qkv.Alo[z] = inlo + z * MPZ;
        qkv.Whi[z] = whi + z * WK2;   qkv.Wlo[z] = wlo + z * WK2;
        qkv.Chi[z] = qkvh + z * MPZ;  qkv.Clo[z] = qkvl + z * MPZ;
        qkv.C[z] = nullptr;
    }
    qkv.bias[0] = b_Q; qkv.bias[1] = b_K; qkv.bias[2] = b_V;
    qkv.scale[0] = 0.125f; qkv.scale[1] = 1.0f; qkv.scale[2] = 1.0f;
    gemm_packed_kernel<1><<<dim3(D_MODEL / 128, M_ROWS / 128, 3), 256, gemmSmem>>>(
        qkv, M_ROWS, D_MODEL);

    // ---- attention (tensor cores + cp.async pipeline, 512 threads)
    const size_t attnSmem = (size_t)ATTN_SMEM_WORDS * 4;   // 108 KB
    cudaFuncSetAttribute(attn_mma_kernel,
                         cudaFuncAttributeMaxDynamicSharedMemorySize, (int)attnSmem);
    attn_mma_kernel<<<dim3(S_LEN / 128, NH, B_SZ), 512, attnSmem>>>(
        qkvh, qkvl, qkvh + MPZ, qkvl + MPZ, qkvh + 2 * MPZ, qkvl + 2 * MPZ,
        attn_ptr, chi, clo, gl, writeAttn);

    if (writeAttn)
        attn_fixup_kernel<<<B_SZ * NH * S_LEN, 256>>>(attn_ptr, gl);

    // ---- output projection (packed ctx -> fp32 out)
    if (writeOut) {
        PGemmArgs og;
        for (int z = 0; z < 3; z++) {
            og.Ahi[z] = chi;           og.Alo[z] = clo;
            og.Whi[z] = whi + 3 * WK2; og.Wlo[z] = wlo + 3 * WK2;
            og.bias[z] = b_O;          og.C[z] = d_out;
            og.Chi[z] = nullptr;       og.Clo[z] = nullptr;
            og.scale[z] = 1.0f;
        }
        gemm_packed_kernel<0><<<dim3(D_MODEL / 128, M_ROWS / 128, 1), 256, gemmSmem>>>(
            og, M_ROWS, D_MODEL);
    }
}